// round 1
// baseline (speedup 1.0000x reference)
#include <cuda_runtime.h>
#include <math.h>

// Problem constants
#define B_   2
#define T_   2048
#define C_   2048
#define H_   16
#define HS_  128
#define NLQ_ 512
#define NLKV_ 512
#define RHD_ 64
#define D_   192   // HS + RHD

// ---------------------------------------------------------------------------
// Static device scratch (allocation-free rule: __device__ globals)
// ---------------------------------------------------------------------------
__device__ float g_cq [B_*T_*NLQ_];                 //  8 MB
__device__ float g_ckv[B_*T_*NLKV_];                //  8 MB
__device__ float g_qc [B_*T_*C_];                   // 33.5 MB
__device__ float g_kc [B_*T_*C_];                   // 33.5 MB
__device__ float g_vt [B_*T_*C_];                   // 33.5 MB
__device__ float g_qr [B_*T_*H_*RHD_];              // 16.8 MB
__device__ float g_kr [B_*T_*RHD_];                 //  1 MB
__device__ float g_q  [B_*H_*T_*D_];                // 50.3 MB  (b,h,t,192)
__device__ float g_k  [B_*H_*T_*D_];                // 50.3 MB  (b,h,t,192)
__device__ float g_v  [B_*H_*T_*HS_];               // 33.5 MB  (b,h,t,128)
__device__ float g_ao [B_*T_*C_];                   // 33.5 MB  (b,t,h*hs)
__device__ float g_scores[(size_t)B_*H_*T_*T_];     // 537 MB   (b,h,t,t)

// ---------------------------------------------------------------------------
// Generic tiled SGEMM, NT form: C[m,n] = sum_k A[m,k] * B[n,k]
// A: (M,K) row-major lda, B: (N,K) row-major ldb, C: (M,N) row-major ldc.
// Batched via blockIdx.z with element strides sA/sB/sC.
// CAUSAL: skip blocks entirely above the diagonal (scores GEMM).
// ---------------------------------------------------------------------------
template<int BM, int BN, int BK, int TM, int TN, bool CAUSAL>
__global__ void __launch_bounds__((BM/TM)*(BN/TN))
gemm_nt(const float* __restrict__ Ab, const float* __restrict__ Bb,
        float* __restrict__ Cb, int M, int N, int K,
        int lda, int ldb, int ldc,
        size_t sA, size_t sB, size_t sC)
{
    constexpr int THREADS = (BM/TM)*(BN/TN);
    const int m0 = blockIdx.y * BM;
    const int n0 = blockIdx.x * BN;
    if (CAUSAL && n0 > m0 + BM - 1) return;   // fully-masked block

    const float* A = Ab + (size_t)blockIdx.z * sA;
    const float* Bm = Bb + (size_t)blockIdx.z * sB;
    float*       Cm = Cb + (size_t)blockIdx.z * sC;

    __shared__ float As[BK][BM];
    __shared__ float Bs[BK][BN];
    const int tid = threadIdx.x;
    const int tr = tid / (BN/TN);
    const int tc = tid % (BN/TN);

    float acc[TM][TN];
    #pragma unroll
    for (int i = 0; i < TM; i++)
        #pragma unroll
        for (int j = 0; j < TN; j++) acc[i][j] = 0.f;

    for (int k0 = 0; k0 < K; k0 += BK) {
        #pragma unroll
        for (int i = tid; i < BM*(BK/4); i += THREADS) {
            int m  = i / (BK/4);
            int kq = (i % (BK/4)) * 4;
            float4 val = make_float4(0.f,0.f,0.f,0.f);
            int gm = m0 + m;
            if (gm < M) val = *(const float4*)(A + (size_t)gm*lda + k0 + kq);
            As[kq+0][m] = val.x; As[kq+1][m] = val.y;
            As[kq+2][m] = val.z; As[kq+3][m] = val.w;
        }
        #pragma unroll
        for (int i = tid; i < BN*(BK/4); i += THREADS) {
            int n  = i / (BK/4);
            int kq = (i % (BK/4)) * 4;
            float4 val = make_float4(0.f,0.f,0.f,0.f);
            int gn = n0 + n;
            if (gn < N) val = *(const float4*)(Bm + (size_t)gn*ldb + k0 + kq);
            Bs[kq+0][n] = val.x; Bs[kq+1][n] = val.y;
            Bs[kq+2][n] = val.z; Bs[kq+3][n] = val.w;
        }
        __syncthreads();
        #pragma unroll
        for (int kk = 0; kk < BK; kk++) {
            float a[TM], bv[TN];
            #pragma unroll
            for (int i = 0; i < TM; i++) a[i]  = As[kk][tr*TM + i];
            #pragma unroll
            for (int j = 0; j < TN; j++) bv[j] = Bs[kk][tc*TN + j];
            #pragma unroll
            for (int i = 0; i < TM; i++)
                #pragma unroll
                for (int j = 0; j < TN; j++) acc[i][j] += a[i] * bv[j];
        }
        __syncthreads();
    }
    #pragma unroll
    for (int i = 0; i < TM; i++) {
        int gm = m0 + tr*TM + i;
        if (gm >= M) continue;
        #pragma unroll
        for (int j = 0; j < TN; j++) {
            int gn = n0 + tc*TN + j;
            if (gn < N) Cm[(size_t)gm*ldc + gn] = acc[i][j];
        }
    }
}

// ---------------------------------------------------------------------------
// attn @ V : NN GEMM, batched over (b,h), causal k-limit per block-row.
// attn: (T,T) rows contiguous; V: (b,h,t,128); out scattered to (b,t,h*128+n)
// ---------------------------------------------------------------------------
template<int BM, int BN, int BK, int TM, int TN>
__global__ void __launch_bounds__((BM/TM)*(BN/TN))
attn_v_gemm(const float* __restrict__ attn, const float* __restrict__ v,
            float* __restrict__ out)
{
    constexpr int THREADS = (BM/TM)*(BN/TN);
    const int z = blockIdx.z, b = z / H_, h = z % H_;
    const float* A  = attn + (size_t)z * T_ * T_;
    const float* Bv = v    + (size_t)z * T_ * HS_;
    const int m0 = blockIdx.y * BM;
    const int kend = m0 + BM;            // causal: attn[m, k>m] == 0; block rows < m0+BM

    __shared__ float As[BK][BM];
    __shared__ float Bs[BK][BN];
    const int tid = threadIdx.x;
    const int tr = tid / (BN/TN);
    const int tc = tid % (BN/TN);

    float acc[TM][TN];
    #pragma unroll
    for (int i = 0; i < TM; i++)
        #pragma unroll
        for (int j = 0; j < TN; j++) acc[i][j] = 0.f;

    for (int k0 = 0; k0 < kend; k0 += BK) {
        #pragma unroll
        for (int i = tid; i < BM*(BK/4); i += THREADS) {
            int m  = i / (BK/4);
            int kq = (i % (BK/4)) * 4;
            float4 val = *(const float4*)(A + (size_t)(m0+m)*T_ + k0 + kq);
            As[kq+0][m] = val.x; As[kq+1][m] = val.y;
            As[kq+2][m] = val.z; As[kq+3][m] = val.w;
        }
        #pragma unroll
        for (int i = tid; i < BK*(BN/4); i += THREADS) {
            int k  = i / (BN/4);
            int nq = (i % (BN/4)) * 4;
            *(float4*)&Bs[k][nq] = *(const float4*)(Bv + (size_t)(k0+k)*HS_ + nq);
        }
        __syncthreads();
        #pragma unroll
        for (int kk = 0; kk < BK; kk++) {
            float a[TM], bv[TN];
            #pragma unroll
            for (int i = 0; i < TM; i++) a[i]  = As[kk][tr*TM + i];
            #pragma unroll
            for (int j = 0; j < TN; j++) bv[j] = Bs[kk][tc*TN + j];
            #pragma unroll
            for (int i = 0; i < TM; i++)
                #pragma unroll
                for (int j = 0; j < TN; j++) acc[i][j] += a[i] * bv[j];
        }
        __syncthreads();
    }
    #pragma unroll
    for (int i = 0; i < TM; i++) {
        int gm = m0 + tr*TM + i;
        #pragma unroll
        for (int j = 0; j < TN; j++) {
            int gn = tc*TN + j;
            out[((size_t)(b*T_ + gm))*C_ + h*HS_ + gn] = acc[i][j];
        }
    }
}

// ---------------------------------------------------------------------------
// Pack + RoPE kernels: build q/k (b,h,t,192) and v (b,h,t,128)
// ---------------------------------------------------------------------------
__global__ void pack_q(const float* __restrict__ qc, const float* __restrict__ qr,
                       const float* __restrict__ cs, const float* __restrict__ sn,
                       float* __restrict__ q)
{
    int idx = blockIdx.x * blockDim.x + threadIdx.x;
    if (idx >= B_*H_*T_*D_) return;
    int d = idx % D_;
    int t = (idx / D_) % T_;
    int h = (idx / (D_*T_)) % H_;
    int b = idx / (D_*T_*H_);
    float val;
    if (d < HS_) {
        val = qc[((size_t)(b*T_ + t))*C_ + h*HS_ + d];
    } else {
        int j = d - HS_;
        int p = j >> 1;
        const float* base = qr + ((size_t)(b*T_ + t))*(H_*RHD_) + h*RHD_ + 2*p;
        float re = base[0], im = base[1];
        float c = cs[t*(RHD_/2) + p], s = sn[t*(RHD_/2) + p];
        val = (j & 1) ? (re*s + im*c) : (re*c - im*s);
    }
    q[idx] = val;
}

__global__ void pack_k(const float* __restrict__ kc, const float* __restrict__ kr,
                       const float* __restrict__ cs, const float* __restrict__ sn,
                       float* __restrict__ k)
{
    int idx = blockIdx.x * blockDim.x + threadIdx.x;
    if (idx >= B_*H_*T_*D_) return;
    int d = idx % D_;
    int t = (idx / D_) % T_;
    int h = (idx / (D_*T_)) % H_;
    int b = idx / (D_*T_*H_);
    float val;
    if (d < HS_) {
        val = kc[((size_t)(b*T_ + t))*C_ + h*HS_ + d];
    } else {
        int j = d - HS_;
        int p = j >> 1;
        const float* base = kr + ((size_t)(b*T_ + t))*RHD_ + 2*p;  // single head, broadcast
        float re = base[0], im = base[1];
        float c = cs[t*(RHD_/2) + p], s = sn[t*(RHD_/2) + p];
        val = (j & 1) ? (re*s + im*c) : (re*c - im*s);
    }
    k[idx] = val;
}

__global__ void pack_v(const float* __restrict__ vt, float* __restrict__ v)
{
    int idx = blockIdx.x * blockDim.x + threadIdx.x;
    if (idx >= B_*H_*T_*HS_) return;
    int d = idx % HS_;
    int t = (idx / HS_) % T_;
    int h = (idx / (HS_*T_)) % H_;
    int b = idx / (HS_*T_*H_);
    v[idx] = vt[((size_t)(b*T_ + t))*C_ + h*HS_ + d];
}

// ---------------------------------------------------------------------------
// Causal softmax, in-place on scores, one block per (b,h,query) row.
// Zeros the masked tail up to this row's 128-block boundary so attn_v_gemm's
// shared per-block k-limit reads only valid zeros.
// ---------------------------------------------------------------------------
__global__ void softmax_causal(float* __restrict__ scores)
{
    const int r = blockIdx.x;
    const int i = r % T_;
    const size_t z = r / T_;
    float* row = scores + z*(size_t)(T_*T_) + (size_t)i*T_;
    const int L = i + 1;
    const float scale = 0.07216878364870323f;  // 1/sqrt(192)
    __shared__ float red[256];
    const int tid = threadIdx.x;

    float lm = -1e30f;
    for (int j = tid; j < L; j += 256) lm = fmaxf(lm, row[j]);
    red[tid] = lm; __syncthreads();
    for (int s = 128; s > 0; s >>= 1) {
        if (tid < s) red[tid] = fmaxf(red[tid], red[tid+s]);
        __syncthreads();
    }
    const float mx = red[0] * scale;
    __syncthreads();

    float ls = 0.f;
    for (int j = tid; j < L; j += 256) {
        float e = __expf(row[j]*scale - mx);
        row[j] = e;
        ls += e;
    }
    red[tid] = ls; __syncthreads();
    for (int s = 128; s > 0; s >>= 1) {
        if (tid < s) red[tid] += red[tid+s];
        __syncthreads();
    }
    const float inv = 1.f / red[0];
    __syncthreads();

    for (int j = tid; j < L; j += 256) row[j] *= inv;
    const int zend = ((i / 128) + 1) * 128;   // attn_v block k-limit for this row
    for (int j = L + tid; j < zend; j += 256) row[j] = 0.f;
}

// ---------------------------------------------------------------------------
// Launch
// ---------------------------------------------------------------------------
extern "C" void kernel_launch(void* const* d_in, const int* in_sizes, int n_in,
                              void* d_out, int out_size)
{
    const float* x    = (const float*)d_in[0];
    const float* fc   = (const float*)d_in[1];
    const float* fs   = (const float*)d_in[2];
    const float* Wdq  = (const float*)d_in[3];
    const float* Wuq  = (const float*)d_in[4];
    const float* Wdkv = (const float*)d_in[5];
    const float* Wuk  = (const float*)d_in[6];
    const float* Wuv  = (const float*)d_in[7];
    const float* Wqr  = (const float*)d_in[8];
    const float* Wkr  = (const float*)d_in[9];
    const float* Wo   = (const float*)d_in[10];
    float* out = (float*)d_out;

    float *cq, *ckv, *qc, *kc, *vt, *qr, *kr, *q, *k, *v, *ao, *sc;
    cudaGetSymbolAddress((void**)&cq,  g_cq);
    cudaGetSymbolAddress((void**)&ckv, g_ckv);
    cudaGetSymbolAddress((void**)&qc,  g_qc);
    cudaGetSymbolAddress((void**)&kc,  g_kc);
    cudaGetSymbolAddress((void**)&vt,  g_vt);
    cudaGetSymbolAddress((void**)&qr,  g_qr);
    cudaGetSymbolAddress((void**)&kr,  g_kr);
    cudaGetSymbolAddress((void**)&q,   g_q);
    cudaGetSymbolAddress((void**)&k,   g_k);
    cudaGetSymbolAddress((void**)&v,   g_v);
    cudaGetSymbolAddress((void**)&ao,  g_ao);
    cudaGetSymbolAddress((void**)&sc,  g_scores);

    const int M = B_ * T_;   // 4096
    dim3 blk(256);
    auto grd = [](int m, int n) { return dim3((n+127)/128, (m+127)/128, 1); };

    // Down/up projections (all NT)
    gemm_nt<128,128,8,8,8,false><<<grd(M, NLQ_),   blk>>>(x,   Wdq,  cq, M, NLQ_,    C_,   C_,   C_,   NLQ_,    0,0,0);
    gemm_nt<128,128,8,8,8,false><<<grd(M, NLKV_),  blk>>>(x,   Wdkv, ckv,M, NLKV_,   C_,   C_,   C_,   NLKV_,   0,0,0);
    gemm_nt<128,128,8,8,8,false><<<grd(M, RHD_),   blk>>>(x,   Wkr,  kr, M, RHD_,    C_,   C_,   C_,   RHD_,    0,0,0);
    gemm_nt<128,128,8,8,8,false><<<grd(M, C_),     blk>>>(cq,  Wuq,  qc, M, C_,      NLQ_, NLQ_, NLQ_, C_,      0,0,0);
    gemm_nt<128,128,8,8,8,false><<<grd(M, H_*RHD_),blk>>>(cq,  Wqr,  qr, M, H_*RHD_, NLQ_, NLQ_, NLQ_, H_*RHD_, 0,0,0);
    gemm_nt<128,128,8,8,8,false><<<grd(M, C_),     blk>>>(ckv, Wuk,  kc, M, C_,      NLKV_,NLKV_,NLKV_,C_,      0,0,0);
    gemm_nt<128,128,8,8,8,false><<<grd(M, C_),     blk>>>(ckv, Wuv,  vt, M, C_,      NLKV_,NLKV_,NLKV_,C_,      0,0,0);

    // RoPE + concat + layout packs
    pack_q<<<(B_*H_*T_*D_  + 255)/256, 256>>>(qc, qr, fc, fs, q);
    pack_k<<<(B_*H_*T_*D_  + 255)/256, 256>>>(kc, kr, fc, fs, k);
    pack_v<<<(B_*H_*T_*HS_ + 255)/256, 256>>>(vt, v);

    // Scores: batched NT over (b,h), causal block skip
    dim3 gs(T_/128, T_/128, B_*H_);
    gemm_nt<128,128,8,8,8,true><<<gs, blk>>>(q, k, sc, T_, T_, D_, D_, D_, T_,
                                             (size_t)T_*D_, (size_t)T_*D_, (size_t)T_*T_);

    // Causal softmax in-place
    softmax_causal<<<B_*H_*T_, 256>>>(sc);

    // attn @ V with causal k-limit, scatter into (b,t,h*hs)
    dim3 gav(1, T_/128, B_*H_);
    attn_v_gemm<128,128,8,8,8><<<gav, blk>>>(sc, v, ao);

    // Output projection
    gemm_nt<128,128,8,8,8,false><<<grd(M, C_), blk>>>(ao, Wo, out, M, C_, C_, C_, C_, C_, 0,0,0);
}

// round 2
// speedup vs baseline: 2.5249x; 2.5249x over previous
#include <cuda_runtime.h>
#include <math.h>

// Problem constants
#define B_   2
#define T_   2048
#define C_   2048
#define H_   16
#define HS_  128
#define NLQ_ 512
#define NLKV_ 512
#define RHD_ 64
#define D_   192   // HS + RHD

// ---------------------------------------------------------------------------
// Static device scratch (allocation-free rule: __device__ globals)
// ---------------------------------------------------------------------------
__device__ float g_cq [B_*T_*NLQ_];
__device__ float g_ckv[B_*T_*NLKV_];
__device__ float g_qc [B_*T_*C_];
__device__ float g_kc [B_*T_*C_];
__device__ float g_vt [B_*T_*C_];
__device__ float g_qr [B_*T_*H_*RHD_];
__device__ float g_kr [B_*T_*RHD_];
__device__ float g_q  [B_*H_*T_*D_];
__device__ float g_k  [B_*H_*T_*D_];
__device__ float g_v  [B_*H_*T_*HS_];
__device__ float g_ao [B_*T_*C_];
__device__ float g_scores[(size_t)B_*H_*T_*T_];

// ---------------------------------------------------------------------------
// tf32 helpers
// ---------------------------------------------------------------------------
__device__ __forceinline__ unsigned f2tf(float f) {
    unsigned u;
    asm("cvt.rna.tf32.f32 %0, %1;" : "=r"(u) : "f"(f));
    return u;
}

__device__ __forceinline__ void mma_tf32(float* d, const unsigned* a, const unsigned* b) {
    asm volatile(
        "mma.sync.aligned.m16n8k8.row.col.f32.tf32.tf32.f32 "
        "{%0,%1,%2,%3}, {%4,%5,%6,%7}, {%8,%9}, {%0,%1,%2,%3};"
        : "+f"(d[0]), "+f"(d[1]), "+f"(d[2]), "+f"(d[3])
        : "r"(a[0]), "r"(a[1]), "r"(a[2]), "r"(a[3]),
          "r"(b[0]), "r"(b[1]));
}

#define BM 128
#define BN 128
#define BKK 16
#define KP 20    // padded k-stride in smem (stride 20 words -> conflict-free quads)

// ---------------------------------------------------------------------------
// Tensor-core GEMM, NT form: C[m,n] = sum_k A[m,k]*B[n,k]
// A:(M,K) lda, B:(N,K) ldb, C:(M,N) ldc, batched over z via strides.
// 256 threads, 8 warps (2m x 4n), warp tile 64x32, mma m16n8k8 tf32.
// ---------------------------------------------------------------------------
template<bool CAUSAL>
__global__ void __launch_bounds__(256, 2)
mma_gemm_nt(const float* __restrict__ Ab, const float* __restrict__ Bb,
            float* __restrict__ Cb, int M, int N, int K,
            int lda, int ldb, int ldc,
            size_t sA, size_t sB, size_t sC)
{
    const int m0 = blockIdx.y * BM;
    const int n0 = blockIdx.x * BN;
    if (CAUSAL && n0 > m0 + BM - 1) return;

    const float* A  = Ab + (size_t)blockIdx.z * sA;
    const float* Bm = Bb + (size_t)blockIdx.z * sB;
    float*       Cm = Cb + (size_t)blockIdx.z * sC;

    __shared__ unsigned As[2][BM * KP];
    __shared__ unsigned Bs[2][BN * KP];

    const int tid  = threadIdx.x;
    const int wid  = tid >> 5;
    const int lane = tid & 31;
    const int g    = lane >> 2;
    const int tig  = lane & 3;
    const int wm0  = (wid >> 2) * 64;
    const int wn0  = (wid & 3) * 32;

    float acc[4][4][4];
    #pragma unroll
    for (int i = 0; i < 4; i++)
        #pragma unroll
        for (int j = 0; j < 4; j++)
            #pragma unroll
            for (int r = 0; r < 4; r++) acc[i][j][r] = 0.f;

    const int lrow = tid >> 2;          // 0..63 (reused with +64 offset)
    const int lkq  = (tid & 3) << 2;    // 0,4,8,12

    float4 ra[2], rb[2];

    auto ldAB = [&](int kt) {
        #pragma unroll
        for (int j = 0; j < 2; j++) {
            int m = lrow + j * 64;
            int gm = m0 + m;
            ra[j] = (gm < M) ? *(const float4*)(A + (size_t)gm * lda + kt * BKK + lkq)
                             : make_float4(0.f, 0.f, 0.f, 0.f);
            int gn = n0 + m;
            rb[j] = (gn < N) ? *(const float4*)(Bm + (size_t)gn * ldb + kt * BKK + lkq)
                             : make_float4(0.f, 0.f, 0.f, 0.f);
        }
    };
    auto stAB = [&](int buf) {
        #pragma unroll
        for (int j = 0; j < 2; j++) {
            int m = lrow + j * 64;
            unsigned* pa = &As[buf][m * KP + lkq];
            pa[0] = f2tf(ra[j].x); pa[1] = f2tf(ra[j].y);
            pa[2] = f2tf(ra[j].z); pa[3] = f2tf(ra[j].w);
            unsigned* pb = &Bs[buf][m * KP + lkq];
            pb[0] = f2tf(rb[j].x); pb[1] = f2tf(rb[j].y);
            pb[2] = f2tf(rb[j].z); pb[3] = f2tf(rb[j].w);
        }
    };

    const int nk = K / BKK;
    ldAB(0);
    stAB(0);
    __syncthreads();

    for (int kt = 0; kt < nk; kt++) {
        int buf = kt & 1;
        if (kt + 1 < nk) ldAB(kt + 1);

        #pragma unroll
        for (int kk = 0; kk < 2; kk++) {
            unsigned af[4][4], bf[4][2];
            #pragma unroll
            for (int ti = 0; ti < 4; ti++) {
                int r0 = (wm0 + ti * 16 + g) * KP + kk * 8 + tig;
                af[ti][0] = As[buf][r0];
                af[ti][1] = As[buf][r0 + 8 * KP];
                af[ti][2] = As[buf][r0 + 4];
                af[ti][3] = As[buf][r0 + 8 * KP + 4];
            }
            #pragma unroll
            for (int tj = 0; tj < 4; tj++) {
                int r0 = (wn0 + tj * 8 + g) * KP + kk * 8 + tig;
                bf[tj][0] = Bs[buf][r0];
                bf[tj][1] = Bs[buf][r0 + 4];
            }
            #pragma unroll
            for (int ti = 0; ti < 4; ti++)
                #pragma unroll
                for (int tj = 0; tj < 4; tj++)
                    mma_tf32(acc[ti][tj], af[ti], bf[tj]);
        }

        if (kt + 1 < nk) {
            stAB(buf ^ 1);
            __syncthreads();
        }
    }

    #pragma unroll
    for (int ti = 0; ti < 4; ti++) {
        int gm = m0 + wm0 + ti * 16 + g;
        #pragma unroll
        for (int tj = 0; tj < 4; tj++) {
            int gn = n0 + wn0 + tj * 8 + tig * 2;
            if (gn < N) {
                if (gm < M)
                    *(float2*)(Cm + (size_t)gm * ldc + gn) =
                        make_float2(acc[ti][tj][0], acc[ti][tj][1]);
                if (gm + 8 < M)
                    *(float2*)(Cm + (size_t)(gm + 8) * ldc + gn) =
                        make_float2(acc[ti][tj][2], acc[ti][tj][3]);
            }
        }
    }
}

// ---------------------------------------------------------------------------
// attn @ V : tensor-core NN GEMM, batched over (b,h), causal k-limit, scatter
// epilogue into (b,t,h*HS+n). attn:(T,T), V:(b,h,t,HS).
// ---------------------------------------------------------------------------
__global__ void __launch_bounds__(256, 2)
mma_attn_v(const float* __restrict__ attn, const float* __restrict__ v,
           float* __restrict__ out)
{
    const int z = blockIdx.z, b = z / H_, h = z % H_;
    const float* A  = attn + (size_t)z * T_ * T_;
    const float* Bv = v    + (size_t)z * T_ * HS_;
    const int m0 = blockIdx.y * BM;
    const int kend = m0 + BM;            // causal: rows need k <= m0+127

    __shared__ unsigned As[2][BM * KP];
    __shared__ unsigned Bs[2][BN * KP];

    const int tid  = threadIdx.x;
    const int wid  = tid >> 5;
    const int lane = tid & 31;
    const int g    = lane >> 2;
    const int tig  = lane & 3;
    const int wm0  = (wid >> 2) * 64;
    const int wn0  = (wid & 3) * 32;

    float acc[4][4][4];
    #pragma unroll
    for (int i = 0; i < 4; i++)
        #pragma unroll
        for (int j = 0; j < 4; j++)
            #pragma unroll
            for (int r = 0; r < 4; r++) acc[i][j][r] = 0.f;

    const int larow = tid >> 2;          // A: 0..63
    const int lakq  = (tid & 3) << 2;
    const int lbk   = tid >> 5;          // B: k row 0..7 (+8)
    const int lbnq  = (tid & 31) << 2;   // n 0..124

    float4 ra[2], rb[2];

    auto ldAB = [&](int kt) {
        #pragma unroll
        for (int j = 0; j < 2; j++) {
            int m = larow + j * 64;
            ra[j] = *(const float4*)(A + (size_t)(m0 + m) * T_ + kt * BKK + lakq);
            int k = lbk + j * 8;
            rb[j] = *(const float4*)(Bv + (size_t)(kt * BKK + k) * HS_ + lbnq);
        }
    };
    auto stAB = [&](int buf) {
        #pragma unroll
        for (int j = 0; j < 2; j++) {
            int m = larow + j * 64;
            unsigned* pa = &As[buf][m * KP + lakq];
            pa[0] = f2tf(ra[j].x); pa[1] = f2tf(ra[j].y);
            pa[2] = f2tf(ra[j].z); pa[3] = f2tf(ra[j].w);
            int k = lbk + j * 8;
            Bs[buf][(lbnq + 0) * KP + k] = f2tf(rb[j].x);
            Bs[buf][(lbnq + 1) * KP + k] = f2tf(rb[j].y);
            Bs[buf][(lbnq + 2) * KP + k] = f2tf(rb[j].z);
            Bs[buf][(lbnq + 3) * KP + k] = f2tf(rb[j].w);
        }
    };

    const int nk = kend / BKK;
    ldAB(0);
    stAB(0);
    __syncthreads();

    for (int kt = 0; kt < nk; kt++) {
        int buf = kt & 1;
        if (kt + 1 < nk) ldAB(kt + 1);

        #pragma unroll
        for (int kk = 0; kk < 2; kk++) {
            unsigned af[4][4], bf[4][2];
            #pragma unroll
            for (int ti = 0; ti < 4; ti++) {
                int r0 = (wm0 + ti * 16 + g) * KP + kk * 8 + tig;
                af[ti][0] = As[buf][r0];
                af[ti][1] = As[buf][r0 + 8 * KP];
                af[ti][2] = As[buf][r0 + 4];
                af[ti][3] = As[buf][r0 + 8 * KP + 4];
            }
            #pragma unroll
            for (int tj = 0; tj < 4; tj++) {
                int r0 = (wn0 + tj * 8 + g) * KP + kk * 8 + tig;
                bf[tj][0] = Bs[buf][r0];
                bf[tj][1] = Bs[buf][r0 + 4];
            }
            #pragma unroll
            for (int ti = 0; ti < 4; ti++)
                #pragma unroll
                for (int tj = 0; tj < 4; tj++)
                    mma_tf32(acc[ti][tj], af[ti], bf[tj]);
        }

        if (kt + 1 < nk) {
            stAB(buf ^ 1);
            __syncthreads();
        }
    }

    #pragma unroll
    for (int ti = 0; ti < 4; ti++) {
        int gm = m0 + wm0 + ti * 16 + g;
        #pragma unroll
        for (int tj = 0; tj < 4; tj++) {
            int gn = wn0 + tj * 8 + tig * 2;
            *(float2*)(out + ((size_t)(b * T_ + gm)) * C_ + h * HS_ + gn) =
                make_float2(acc[ti][tj][0], acc[ti][tj][1]);
            *(float2*)(out + ((size_t)(b * T_ + gm + 8)) * C_ + h * HS_ + gn) =
                make_float2(acc[ti][tj][2], acc[ti][tj][3]);
        }
    }
}

// ---------------------------------------------------------------------------
// Pack + RoPE kernels
// ---------------------------------------------------------------------------
__global__ void pack_q(const float* __restrict__ qc, const float* __restrict__ qr,
                       const float* __restrict__ cs, const float* __restrict__ sn,
                       float* __restrict__ q)
{
    int idx = blockIdx.x * blockDim.x + threadIdx.x;
    if (idx >= B_*H_*T_*D_) return;
    int d = idx % D_;
    int t = (idx / D_) % T_;
    int h = (idx / (D_*T_)) % H_;
    int b = idx / (D_*T_*H_);
    float val;
    if (d < HS_) {
        val = qc[((size_t)(b*T_ + t))*C_ + h*HS_ + d];
    } else {
        int j = d - HS_;
        int p = j >> 1;
        const float* base = qr + ((size_t)(b*T_ + t))*(H_*RHD_) + h*RHD_ + 2*p;
        float re = base[0], im = base[1];
        float c = cs[t*(RHD_/2) + p], s = sn[t*(RHD_/2) + p];
        val = (j & 1) ? (re*s + im*c) : (re*c - im*s);
    }
    q[idx] = val;
}

__global__ void pack_k(const float* __restrict__ kc, const float* __restrict__ kr,
                       const float* __restrict__ cs, const float* __restrict__ sn,
                       float* __restrict__ k)
{
    int idx = blockIdx.x * blockDim.x + threadIdx.x;
    if (idx >= B_*H_*T_*D_) return;
    int d = idx % D_;
    int t = (idx / D_) % T_;
    int h = (idx / (D_*T_)) % H_;
    int b = idx / (D_*T_*H_);
    float val;
    if (d < HS_) {
        val = kc[((size_t)(b*T_ + t))*C_ + h*HS_ + d];
    } else {
        int j = d - HS_;
        int p = j >> 1;
        const float* base = kr + ((size_t)(b*T_ + t))*RHD_ + 2*p;
        float re = base[0], im = base[1];
        float c = cs[t*(RHD_/2) + p], s = sn[t*(RHD_/2) + p];
        val = (j & 1) ? (re*s + im*c) : (re*c - im*s);
    }
    k[idx] = val;
}

__global__ void pack_v(const float* __restrict__ vt, float* __restrict__ v)
{
    int idx = blockIdx.x * blockDim.x + threadIdx.x;
    if (idx >= B_*H_*T_*HS_) return;
    int d = idx % HS_;
    int t = (idx / HS_) % T_;
    int h = (idx / (HS_*T_)) % H_;
    int b = idx / (HS_*T_*H_);
    v[idx] = vt[((size_t)(b*T_ + t))*C_ + h*HS_ + d];
}

// ---------------------------------------------------------------------------
// Causal softmax (in-place), zeroing masked tail to 128-block boundary.
// ---------------------------------------------------------------------------
__global__ void softmax_causal(float* __restrict__ scores)
{
    const int r = blockIdx.x;
    const int i = r % T_;
    const size_t z = r / T_;
    float* row = scores + z*(size_t)(T_*T_) + (size_t)i*T_;
    const int L = i + 1;
    const float scale = 0.07216878364870323f;  // 1/sqrt(192)
    __shared__ float red[256];
    const int tid = threadIdx.x;

    float lm = -1e30f;
    for (int j = tid; j < L; j += 256) lm = fmaxf(lm, row[j]);
    red[tid] = lm; __syncthreads();
    for (int s = 128; s > 0; s >>= 1) {
        if (tid < s) red[tid] = fmaxf(red[tid], red[tid+s]);
        __syncthreads();
    }
    const float mx = red[0] * scale;
    __syncthreads();

    float ls = 0.f;
    for (int j = tid; j < L; j += 256) {
        float e = __expf(row[j]*scale - mx);
        row[j] = e;
        ls += e;
    }
    red[tid] = ls; __syncthreads();
    for (int s = 128; s > 0; s >>= 1) {
        if (tid < s) red[tid] += red[tid+s];
        __syncthreads();
    }
    const float inv = 1.f / red[0];
    __syncthreads();

    for (int j = tid; j < L; j += 256) row[j] *= inv;
    const int zend = ((i / 128) + 1) * 128;
    for (int j = L + tid; j < zend; j += 256) row[j] = 0.f;
}

// ---------------------------------------------------------------------------
// Launch
// ---------------------------------------------------------------------------
extern "C" void kernel_launch(void* const* d_in, const int* in_sizes, int n_in,
                              void* d_out, int out_size)
{
    const float* x    = (const float*)d_in[0];
    const float* fc   = (const float*)d_in[1];
    const float* fs   = (const float*)d_in[2];
    const float* Wdq  = (const float*)d_in[3];
    const float* Wuq  = (const float*)d_in[4];
    const float* Wdkv = (const float*)d_in[5];
    const float* Wuk  = (const float*)d_in[6];
    const float* Wuv  = (const float*)d_in[7];
    const float* Wqr  = (const float*)d_in[8];
    const float* Wkr  = (const float*)d_in[9];
    const float* Wo   = (const float*)d_in[10];
    float* out = (float*)d_out;

    float *cq, *ckv, *qc, *kc, *vt, *qr, *kr, *q, *k, *v, *ao, *sc;
    cudaGetSymbolAddress((void**)&cq,  g_cq);
    cudaGetSymbolAddress((void**)&ckv, g_ckv);
    cudaGetSymbolAddress((void**)&qc,  g_qc);
    cudaGetSymbolAddress((void**)&kc,  g_kc);
    cudaGetSymbolAddress((void**)&vt,  g_vt);
    cudaGetSymbolAddress((void**)&qr,  g_qr);
    cudaGetSymbolAddress((void**)&kr,  g_kr);
    cudaGetSymbolAddress((void**)&q,   g_q);
    cudaGetSymbolAddress((void**)&k,   g_k);
    cudaGetSymbolAddress((void**)&v,   g_v);
    cudaGetSymbolAddress((void**)&ao,  g_ao);
    cudaGetSymbolAddress((void**)&sc,  g_scores);

    const int M = B_ * T_;   // 4096
    dim3 blk(256);
    auto grd = [](int m, int n) { return dim3((n+127)/128, (m+127)/128, 1); };

    // Projections (NT, tf32 tensor cores)
    mma_gemm_nt<false><<<grd(M, NLQ_),   blk>>>(x,   Wdq,  cq, M, NLQ_,    C_,   C_,   C_,   NLQ_,    0,0,0);
    mma_gemm_nt<false><<<grd(M, NLKV_),  blk>>>(x,   Wdkv, ckv,M, NLKV_,   C_,   C_,   C_,   NLKV_,   0,0,0);
    mma_gemm_nt<false><<<grd(M, RHD_),   blk>>>(x,   Wkr,  kr, M, RHD_,    C_,   C_,   C_,   RHD_,    0,0,0);
    mma_gemm_nt<false><<<grd(M, C_),     blk>>>(cq,  Wuq,  qc, M, C_,      NLQ_, NLQ_, NLQ_, C_,      0,0,0);
    mma_gemm_nt<false><<<grd(M, H_*RHD_),blk>>>(cq,  Wqr,  qr, M, H_*RHD_, NLQ_, NLQ_, NLQ_, H_*RHD_, 0,0,0);
    mma_gemm_nt<false><<<grd(M, C_),     blk>>>(ckv, Wuk,  kc, M, C_,      NLKV_,NLKV_,NLKV_,C_,      0,0,0);
    mma_gemm_nt<false><<<grd(M, C_),     blk>>>(ckv, Wuv,  vt, M, C_,      NLKV_,NLKV_,NLKV_,C_,      0,0,0);

    // RoPE + concat + layout packs
    pack_q<<<(B_*H_*T_*D_  + 255)/256, 256>>>(qc, qr, fc, fs, q);
    pack_k<<<(B_*H_*T_*D_  + 255)/256, 256>>>(kc, kr, fc, fs, k);
    pack_v<<<(B_*H_*T_*HS_ + 255)/256, 256>>>(vt, v);

    // Scores: batched NT over (b,h), causal block skip
    dim3 gs(T_/128, T_/128, B_*H_);
    mma_gemm_nt<true><<<gs, blk>>>(q, k, sc, T_, T_, D_, D_, D_, T_,
                                   (size_t)T_*D_, (size_t)T_*D_, (size_t)T_*T_);

    // Causal softmax in-place
    softmax_causal<<<B_*H_*T_, 256>>>(sc);

    // attn @ V (tensor cores), scatter into (b,t,h*hs)
    dim3 gav(1, T_/128, B_*H_);
    mma_attn_v<<<gav, blk>>>(sc, v, ao);

    // Output projection
    mma_gemm_nt<false><<<grd(M, C_), blk>>>(ao, Wo, out, M, C_, C_, C_, C_, C_, 0,0,0);
}

// round 3
// speedup vs baseline: 2.9870x; 1.1830x over previous
#include <cuda_runtime.h>
#include <math.h>

// Problem constants
#define B_   2
#define T_   2048
#define C_   2048
#define H_   16
#define HS_  128
#define NLQ_ 512
#define NLKV_ 512
#define RHD_ 64
#define D_   192   // HS + RHD

// ---------------------------------------------------------------------------
// Static device scratch
// ---------------------------------------------------------------------------
__device__ float g_cq [B_*T_*NLQ_];
__device__ float g_ckv[B_*T_*NLKV_];
__device__ float g_qc [B_*T_*C_];
__device__ float g_kc [B_*T_*C_];
__device__ float g_vt [B_*T_*C_];
__device__ float g_qr [B_*T_*H_*RHD_];
__device__ float g_kr [B_*T_*RHD_];
__device__ float g_q  [B_*H_*T_*D_];
__device__ float g_k  [B_*H_*T_*D_];
__device__ float g_v  [B_*H_*T_*HS_];
__device__ float g_ao [B_*T_*C_];

// ---------------------------------------------------------------------------
// tf32 helpers
// ---------------------------------------------------------------------------
__device__ __forceinline__ unsigned f2tf(float f) {
    unsigned u;
    asm("cvt.rna.tf32.f32 %0, %1;" : "=r"(u) : "f"(f));
    return u;
}

__device__ __forceinline__ void mma_tf32(float* d, const unsigned* a, const unsigned* b) {
    asm volatile(
        "mma.sync.aligned.m16n8k8.row.col.f32.tf32.tf32.f32 "
        "{%0,%1,%2,%3}, {%4,%5,%6,%7}, {%8,%9}, {%0,%1,%2,%3};"
        : "+f"(d[0]), "+f"(d[1]), "+f"(d[2]), "+f"(d[3])
        : "r"(a[0]), "r"(a[1]), "r"(a[2]), "r"(a[3]),
          "r"(b[0]), "r"(b[1]));
}

#define BM 128
#define BN 128
#define BKK 16
#define KP 20    // padded k-stride (words) for GEMM smem tiles

// ---------------------------------------------------------------------------
// Tensor-core GEMM, NT form (projections + output projection)
// ---------------------------------------------------------------------------
template<bool CAUSAL>
__global__ void __launch_bounds__(256, 2)
mma_gemm_nt(const float* __restrict__ Ab, const float* __restrict__ Bb,
            float* __restrict__ Cb, int M, int N, int K,
            int lda, int ldb, int ldc,
            size_t sA, size_t sB, size_t sC)
{
    const int m0 = blockIdx.y * BM;
    const int n0 = blockIdx.x * BN;
    if (CAUSAL && n0 > m0 + BM - 1) return;

    const float* A  = Ab + (size_t)blockIdx.z * sA;
    const float* Bm = Bb + (size_t)blockIdx.z * sB;
    float*       Cm = Cb + (size_t)blockIdx.z * sC;

    __shared__ unsigned As[2][BM * KP];
    __shared__ unsigned Bs[2][BN * KP];

    const int tid  = threadIdx.x;
    const int wid  = tid >> 5;
    const int lane = tid & 31;
    const int g    = lane >> 2;
    const int tig  = lane & 3;
    const int wm0  = (wid >> 2) * 64;
    const int wn0  = (wid & 3) * 32;

    float acc[4][4][4];
    #pragma unroll
    for (int i = 0; i < 4; i++)
        #pragma unroll
        for (int j = 0; j < 4; j++)
            #pragma unroll
            for (int r = 0; r < 4; r++) acc[i][j][r] = 0.f;

    const int lrow = tid >> 2;
    const int lkq  = (tid & 3) << 2;

    float4 ra[2], rb[2];

    auto ldAB = [&](int kt) {
        #pragma unroll
        for (int j = 0; j < 2; j++) {
            int m = lrow + j * 64;
            int gm = m0 + m;
            ra[j] = (gm < M) ? *(const float4*)(A + (size_t)gm * lda + kt * BKK + lkq)
                             : make_float4(0.f, 0.f, 0.f, 0.f);
            int gn = n0 + m;
            rb[j] = (gn < N) ? *(const float4*)(Bm + (size_t)gn * ldb + kt * BKK + lkq)
                             : make_float4(0.f, 0.f, 0.f, 0.f);
        }
    };
    auto stAB = [&](int buf) {
        #pragma unroll
        for (int j = 0; j < 2; j++) {
            int m = lrow + j * 64;
            unsigned* pa = &As[buf][m * KP + lkq];
            pa[0] = f2tf(ra[j].x); pa[1] = f2tf(ra[j].y);
            pa[2] = f2tf(ra[j].z); pa[3] = f2tf(ra[j].w);
            unsigned* pb = &Bs[buf][m * KP + lkq];
            pb[0] = f2tf(rb[j].x); pb[1] = f2tf(rb[j].y);
            pb[2] = f2tf(rb[j].z); pb[3] = f2tf(rb[j].w);
        }
    };

    const int nk = K / BKK;
    ldAB(0);
    stAB(0);
    __syncthreads();

    for (int kt = 0; kt < nk; kt++) {
        int buf = kt & 1;
        if (kt + 1 < nk) ldAB(kt + 1);

        #pragma unroll
        for (int kk = 0; kk < 2; kk++) {
            unsigned af[4][4], bf[4][2];
            #pragma unroll
            for (int ti = 0; ti < 4; ti++) {
                int r0 = (wm0 + ti * 16 + g) * KP + kk * 8 + tig;
                af[ti][0] = As[buf][r0];
                af[ti][1] = As[buf][r0 + 8 * KP];
                af[ti][2] = As[buf][r0 + 4];
                af[ti][3] = As[buf][r0 + 8 * KP + 4];
            }
            #pragma unroll
            for (int tj = 0; tj < 4; tj++) {
                int r0 = (wn0 + tj * 8 + g) * KP + kk * 8 + tig;
                bf[tj][0] = Bs[buf][r0];
                bf[tj][1] = Bs[buf][r0 + 4];
            }
            #pragma unroll
            for (int ti = 0; ti < 4; ti++)
                #pragma unroll
                for (int tj = 0; tj < 4; tj++)
                    mma_tf32(acc[ti][tj], af[ti], bf[tj]);
        }

        if (kt + 1 < nk) {
            stAB(buf ^ 1);
            __syncthreads();
        }
    }

    #pragma unroll
    for (int ti = 0; ti < 4; ti++) {
        int gm = m0 + wm0 + ti * 16 + g;
        #pragma unroll
        for (int tj = 0; tj < 4; tj++) {
            int gn = n0 + wn0 + tj * 8 + tig * 2;
            if (gn < N) {
                if (gm < M)
                    *(float2*)(Cm + (size_t)gm * ldc + gn) =
                        make_float2(acc[ti][tj][0], acc[ti][tj][1]);
                if (gm + 8 < M)
                    *(float2*)(Cm + (size_t)(gm + 8) * ldc + gn) =
                        make_float2(acc[ti][tj][2], acc[ti][tj][3]);
            }
        }
    }
}

// ---------------------------------------------------------------------------
// Fused flash attention (tf32 tensor cores, online softmax).
// Grid: x = b*H+h (32), y = Q tile (16, reversed for heavy-first scheduling).
// 256 threads = 8 warps; each warp owns 16 Q rows and the full tile width.
// Q tile 128x192 resident in smem; K/V tiles of 64 keys streamed.
// P (softmaxed probs) round-trips through per-warp-private smem region.
// ---------------------------------------------------------------------------
#define QP  196   // 192 + 4 pad (words): conflict-free fragment LDS
#define KP2 196
#define VP  68    // 64 + 4 pad
#define PP  68

#define FLASH_SMEM_WORDS (128*QP + 64*KP2 + 128*VP + 128*PP)   // 55040
#define FLASH_SMEM_BYTES (FLASH_SMEM_WORDS * 4)                // 220160

__global__ void __launch_bounds__(256, 1)
flash_attn(const float* __restrict__ qg, const float* __restrict__ kg,
           const float* __restrict__ vg, float* __restrict__ ao)
{
    extern __shared__ unsigned smx[];
    unsigned* Qs = smx;                  // [row][k]  128 x QP
    unsigned* Ks = Qs + 128*QP;          // [key][k]   64 x KP2
    unsigned* Vs = Ks + 64*KP2;          // [d][key]  128 x VP  (transposed)
    unsigned* Ps = Vs + 128*VP;          // [row][key] 128 x PP

    const int z  = blockIdx.x;                       // b*H + h
    const int iy = (int)gridDim.y - 1 - blockIdx.y;  // heavy tiles first
    const int q0 = iy * 128;
    const int b = z / H_, h = z % H_;

    const float* Qg = qg + (size_t)z * T_ * D_;
    const float* Kg = kg + (size_t)z * T_ * D_;
    const float* Vg = vg + (size_t)z * T_ * HS_;

    const int tid = threadIdx.x;
    const int wid = tid >> 5, lane = tid & 31;
    const int g = lane >> 2, tig = lane & 3;
    const int qrow0 = q0 + wid * 16 + g;   // this thread's row (and +8)

    // Load Q tile (128 x 192) -> tf32 smem
    #pragma unroll
    for (int it = 0; it < 24; it++) {
        int idx = tid + it * 256;
        int row = idx / 48, kq = (idx % 48) * 4;
        float4 v4 = *(const float4*)(Qg + (size_t)(q0 + row) * D_ + kq);
        unsigned* p = &Qs[row * QP + kq];
        p[0] = f2tf(v4.x); p[1] = f2tf(v4.y); p[2] = f2tf(v4.z); p[3] = f2tf(v4.w);
    }

    float m_i[2] = {-1e30f, -1e30f};
    float l_i[2] = {0.f, 0.f};
    float o[16][4];
    #pragma unroll
    for (int j = 0; j < 16; j++)
        #pragma unroll
        for (int r = 0; r < 4; r++) o[j][r] = 0.f;

    const int nkt = 2 * iy + 2;     // causal: tiles of 64 keys
    const float scale = 0.07216878364870323f;  // 1/sqrt(192)

    for (int kt = 0; kt < nkt; kt++) {
        __syncthreads();   // prev PV (and Q-tile fill) complete before refill

        // K tile 64 x 192
        #pragma unroll
        for (int it = 0; it < 12; it++) {
            int idx = tid + it * 256;
            int row = idx / 48, kq = (idx % 48) * 4;
            float4 v4 = *(const float4*)(Kg + (size_t)(kt * 64 + row) * D_ + kq);
            unsigned* p = &Ks[row * KP2 + kq];
            p[0] = f2tf(v4.x); p[1] = f2tf(v4.y); p[2] = f2tf(v4.z); p[3] = f2tf(v4.w);
        }
        // V tile 64 x 128, stored transposed [d][key]
        #pragma unroll
        for (int it = 0; it < 8; it++) {
            int idx = tid + it * 256;
            int kp = idx / 32, dq = (idx % 32) * 4;
            float4 v4 = *(const float4*)(Vg + (size_t)(kt * 64 + kp) * HS_ + dq);
            Vs[(dq + 0) * VP + kp] = f2tf(v4.x);
            Vs[(dq + 1) * VP + kp] = f2tf(v4.y);
            Vs[(dq + 2) * VP + kp] = f2tf(v4.z);
            Vs[(dq + 3) * VP + kp] = f2tf(v4.w);
        }
        __syncthreads();

        // S = Q K^T : warp tile m16 x n64, k = 192
        float s[8][4];
        #pragma unroll
        for (int j = 0; j < 8; j++)
            #pragma unroll
            for (int r = 0; r < 4; r++) s[j][r] = 0.f;

        #pragma unroll
        for (int kk = 0; kk < 24; kk++) {
            unsigned a[4];
            int r0 = (wid * 16 + g) * QP + kk * 8 + tig;
            a[0] = Qs[r0];          a[1] = Qs[r0 + 8 * QP];
            a[2] = Qs[r0 + 4];      a[3] = Qs[r0 + 8 * QP + 4];
            #pragma unroll
            for (int j = 0; j < 8; j++) {
                unsigned bq[2];
                int rb = (j * 8 + g) * KP2 + kk * 8 + tig;
                bq[0] = Ks[rb]; bq[1] = Ks[rb + 4];
                mma_tf32(s[j], a, bq);
            }
        }

        // Online softmax (rows g and g+8 of the warp's m16 tile)
        const bool diag = (kt >= 2 * iy);   // only last two tiles touch diagonal
        #pragma unroll
        for (int r2 = 0; r2 < 2; r2++) {
            const int row = qrow0 + r2 * 8;
            float mx = -1e30f;
            #pragma unroll
            for (int j = 0; j < 8; j++) {
                #pragma unroll
                for (int c = 0; c < 2; c++) {
                    int r = r2 * 2 + c;
                    float v = s[j][r] * scale;
                    if (diag) {
                        int col = kt * 64 + j * 8 + 2 * tig + c;
                        if (col > row) v = -1e30f;
                    }
                    s[j][r] = v;
                    mx = fmaxf(mx, v);
                }
            }
            mx = fmaxf(mx, __shfl_xor_sync(0xffffffffu, mx, 1));
            mx = fmaxf(mx, __shfl_xor_sync(0xffffffffu, mx, 2));
            float mnew = fmaxf(m_i[r2], mx);
            float alpha = __expf(m_i[r2] - mnew);
            m_i[r2] = mnew;

            float ls = 0.f;
            #pragma unroll
            for (int j = 0; j < 8; j++) {
                #pragma unroll
                for (int c = 0; c < 2; c++) {
                    int r = r2 * 2 + c;
                    float p = __expf(s[j][r] - mnew);
                    s[j][r] = p;
                    ls += p;
                }
            }
            ls += __shfl_xor_sync(0xffffffffu, ls, 1);
            ls += __shfl_xor_sync(0xffffffffu, ls, 2);
            l_i[r2] = l_i[r2] * alpha + ls;

            #pragma unroll
            for (int j = 0; j < 16; j++) {
                o[j][r2 * 2 + 0] *= alpha;
                o[j][r2 * 2 + 1] *= alpha;
            }
        }

        // P -> smem (per-warp-private rows; acc layout -> A-fragment layout)
        {
            int base0 = (wid * 16 + g) * PP;
            int base1 = (wid * 16 + g + 8) * PP;
            #pragma unroll
            for (int j = 0; j < 8; j++) {
                int cc = j * 8 + 2 * tig;
                Ps[base0 + cc    ] = f2tf(s[j][0]);
                Ps[base0 + cc + 1] = f2tf(s[j][1]);
                Ps[base1 + cc    ] = f2tf(s[j][2]);
                Ps[base1 + cc + 1] = f2tf(s[j][3]);
            }
        }
        __syncwarp();

        // O += P V : warp tile m16 x n128, k = 64
        #pragma unroll
        for (int kk = 0; kk < 8; kk++) {
            unsigned a[4];
            int r0 = (wid * 16 + g) * PP + kk * 8 + tig;
            a[0] = Ps[r0];          a[1] = Ps[r0 + 8 * PP];
            a[2] = Ps[r0 + 4];      a[3] = Ps[r0 + 8 * PP + 4];
            #pragma unroll
            for (int j = 0; j < 16; j++) {
                unsigned bq[2];
                int rb = (j * 8 + g) * VP + kk * 8 + tig;
                bq[0] = Vs[rb]; bq[1] = Vs[rb + 4];
                mma_tf32(o[j], a, bq);
            }
        }
    }

    // Epilogue: normalize and scatter into (b, t, h*HS + d)
    const float inv0 = 1.f / l_i[0];
    const float inv1 = 1.f / l_i[1];
    #pragma unroll
    for (int j = 0; j < 16; j++) {
        int d = j * 8 + 2 * tig;
        size_t base0 = ((size_t)(b * T_ + qrow0    )) * C_ + h * HS_ + d;
        size_t base1 = ((size_t)(b * T_ + qrow0 + 8)) * C_ + h * HS_ + d;
        *(float2*)(ao + base0) = make_float2(o[j][0] * inv0, o[j][1] * inv0);
        *(float2*)(ao + base1) = make_float2(o[j][2] * inv1, o[j][3] * inv1);
    }
}

// ---------------------------------------------------------------------------
// Pack + RoPE kernels
// ---------------------------------------------------------------------------
__global__ void pack_q(const float* __restrict__ qc, const float* __restrict__ qr,
                       const float* __restrict__ cs, const float* __restrict__ sn,
                       float* __restrict__ q)
{
    int idx = blockIdx.x * blockDim.x + threadIdx.x;
    if (idx >= B_*H_*T_*D_) return;
    int d = idx % D_;
    int t = (idx / D_) % T_;
    int h = (idx / (D_*T_)) % H_;
    int b = idx / (D_*T_*H_);
    float val;
    if (d < HS_) {
        val = qc[((size_t)(b*T_ + t))*C_ + h*HS_ + d];
    } else {
        int j = d - HS_;
        int p = j >> 1;
        const float* base = qr + ((size_t)(b*T_ + t))*(H_*RHD_) + h*RHD_ + 2*p;
        float re = base[0], im = base[1];
        float c = cs[t*(RHD_/2) + p], s = sn[t*(RHD_/2) + p];
        val = (j & 1) ? (re*s + im*c) : (re*c - im*s);
    }
    q[idx] = val;
}

__global__ void pack_k(const float* __restrict__ kc, const float* __restrict__ kr,
                       const float* __restrict__ cs, const float* __restrict__ sn,
                       float* __restrict__ k)
{
    int idx = blockIdx.x * blockDim.x + threadIdx.x;
    if (idx >= B_*H_*T_*D_) return;
    int d = idx % D_;
    int t = (idx / D_) % T_;
    int h = (idx / (D_*T_)) % H_;
    int b = idx / (D_*T_*H_);
    float val;
    if (d < HS_) {
        val = kc[((size_t)(b*T_ + t))*C_ + h*HS_ + d];
    } else {
        int j = d - HS_;
        int p = j >> 1;
        const float* base = kr + ((size_t)(b*T_ + t))*RHD_ + 2*p;
        float re = base[0], im = base[1];
        float c = cs[t*(RHD_/2) + p], s = sn[t*(RHD_/2) + p];
        val = (j & 1) ? (re*s + im*c) : (re*c - im*s);
    }
    k[idx] = val;
}

__global__ void pack_v(const float* __restrict__ vt, float* __restrict__ v)
{
    int idx = blockIdx.x * blockDim.x + threadIdx.x;
    if (idx >= B_*H_*T_*HS_) return;
    int d = idx % HS_;
    int t = (idx / HS_) % T_;
    int h = (idx / (HS_*T_)) % H_;
    int b = idx / (HS_*T_*H_);
    v[idx] = vt[((size_t)(b*T_ + t))*C_ + h*HS_ + d];
}

// ---------------------------------------------------------------------------
// Launch
// ---------------------------------------------------------------------------
extern "C" void kernel_launch(void* const* d_in, const int* in_sizes, int n_in,
                              void* d_out, int out_size)
{
    const float* x    = (const float*)d_in[0];
    const float* fc   = (const float*)d_in[1];
    const float* fs   = (const float*)d_in[2];
    const float* Wdq  = (const float*)d_in[3];
    const float* Wuq  = (const float*)d_in[4];
    const float* Wdkv = (const float*)d_in[5];
    const float* Wuk  = (const float*)d_in[6];
    const float* Wuv  = (const float*)d_in[7];
    const float* Wqr  = (const float*)d_in[8];
    const float* Wkr  = (const float*)d_in[9];
    const float* Wo   = (const float*)d_in[10];
    float* out = (float*)d_out;

    float *cq, *ckv, *qc, *kc, *vt, *qr, *kr, *q, *k, *v, *ao;
    cudaGetSymbolAddress((void**)&cq,  g_cq);
    cudaGetSymbolAddress((void**)&ckv, g_ckv);
    cudaGetSymbolAddress((void**)&qc,  g_qc);
    cudaGetSymbolAddress((void**)&kc,  g_kc);
    cudaGetSymbolAddress((void**)&vt,  g_vt);
    cudaGetSymbolAddress((void**)&qr,  g_qr);
    cudaGetSymbolAddress((void**)&kr,  g_kr);
    cudaGetSymbolAddress((void**)&q,   g_q);
    cudaGetSymbolAddress((void**)&k,   g_k);
    cudaGetSymbolAddress((void**)&v,   g_v);
    cudaGetSymbolAddress((void**)&ao,  g_ao);

    static bool attr_set = false;
    if (!attr_set) {
        cudaFuncSetAttribute(flash_attn, cudaFuncAttributeMaxDynamicSharedMemorySize,
                             FLASH_SMEM_BYTES);
        attr_set = true;
    }

    const int M = B_ * T_;   // 4096
    dim3 blk(256);
    auto grd = [](int m, int n) { return dim3((n+127)/128, (m+127)/128, 1); };

    // Projections (NT, tf32 tensor cores)
    mma_gemm_nt<false><<<grd(M, NLQ_),   blk>>>(x,   Wdq,  cq, M, NLQ_,    C_,   C_,   C_,   NLQ_,    0,0,0);
    mma_gemm_nt<false><<<grd(M, NLKV_),  blk>>>(x,   Wdkv, ckv,M, NLKV_,   C_,   C_,   C_,   NLKV_,   0,0,0);
    mma_gemm_nt<false><<<grd(M, RHD_),   blk>>>(x,   Wkr,  kr, M, RHD_,    C_,   C_,   C_,   RHD_,    0,0,0);
    mma_gemm_nt<false><<<grd(M, C_),     blk>>>(cq,  Wuq,  qc, M, C_,      NLQ_, NLQ_, NLQ_, C_,      0,0,0);
    mma_gemm_nt<false><<<grd(M, H_*RHD_),blk>>>(cq,  Wqr,  qr, M, H_*RHD_, NLQ_, NLQ_, NLQ_, H_*RHD_, 0,0,0);
    mma_gemm_nt<false><<<grd(M, C_),     blk>>>(ckv, Wuk,  kc, M, C_,      NLKV_,NLKV_,NLKV_,C_,      0,0,0);
    mma_gemm_nt<false><<<grd(M, C_),     blk>>>(ckv, Wuv,  vt, M, C_,      NLKV_,NLKV_,NLKV_,C_,      0,0,0);

    // RoPE + concat + layout packs
    pack_q<<<(B_*H_*T_*D_  + 255)/256, 256>>>(qc, qr, fc, fs, q);
    pack_k<<<(B_*H_*T_*D_  + 255)/256, 256>>>(kc, kr, fc, fs, k);
    pack_v<<<(B_*H_*T_*HS_ + 255)/256, 256>>>(vt, v);

    // Fused flash attention (scores + softmax + attn@V)
    dim3 gfa(B_ * H_, T_ / 128);
    flash_attn<<<gfa, blk, FLASH_SMEM_BYTES>>>(q, k, v, ao);

    // Output projection
    mma_gemm_nt<false><<<grd(M, C_), blk>>>(ao, Wo, out, M, C_, C_, C_, C_, C_, 0,0,0);
}

// round 4
// speedup vs baseline: 3.0025x; 1.0052x over previous
#include <cuda_runtime.h>
#include <math.h>

// Problem constants
#define B_   2
#define T_   2048
#define C_   2048
#define H_   16
#define HS_  128
#define NLQ_ 512
#define NLKV_ 512
#define RHD_ 64
#define D_   192   // HS + RHD

// ---------------------------------------------------------------------------
// Static device scratch
// ---------------------------------------------------------------------------
__device__ float g_cq [B_*T_*NLQ_];
__device__ float g_ckv[B_*T_*NLKV_];
__device__ float g_qc [B_*T_*C_];
__device__ float g_kc [B_*T_*C_];
__device__ float g_vt [B_*T_*C_];
__device__ float g_qr [B_*T_*H_*RHD_];
__device__ float g_kr [B_*T_*RHD_];
__device__ float g_q  [B_*H_*T_*D_];
__device__ float g_k  [B_*H_*T_*D_];
__device__ float g_v  [B_*H_*T_*HS_];
__device__ float g_ao [B_*T_*C_];

// ---------------------------------------------------------------------------
// tf32 helpers
// ---------------------------------------------------------------------------
__device__ __forceinline__ unsigned f2tf(float f) {
    unsigned u;
    asm("cvt.rna.tf32.f32 %0, %1;" : "=r"(u) : "f"(f));
    return u;
}

__device__ __forceinline__ void mma_tf32(float* d, const unsigned* a, const unsigned* b) {
    asm volatile(
        "mma.sync.aligned.m16n8k8.row.col.f32.tf32.tf32.f32 "
        "{%0,%1,%2,%3}, {%4,%5,%6,%7}, {%8,%9}, {%0,%1,%2,%3};"
        : "+f"(d[0]), "+f"(d[1]), "+f"(d[2]), "+f"(d[3])
        : "r"(a[0]), "r"(a[1]), "r"(a[2]), "r"(a[3]),
          "r"(b[0]), "r"(b[1]));
}

#define BM 128
#define BN 128
#define BKK 16
#define KP 20    // padded k-stride (words) for GEMM smem tiles

// ---------------------------------------------------------------------------
// Tensor-core GEMM, NT form (projections + output projection)
// ---------------------------------------------------------------------------
template<bool CAUSAL>
__global__ void __launch_bounds__(256, 2)
mma_gemm_nt(const float* __restrict__ Ab, const float* __restrict__ Bb,
            float* __restrict__ Cb, int M, int N, int K,
            int lda, int ldb, int ldc,
            size_t sA, size_t sB, size_t sC)
{
    const int m0 = blockIdx.y * BM;
    const int n0 = blockIdx.x * BN;
    if (CAUSAL && n0 > m0 + BM - 1) return;

    const float* A  = Ab + (size_t)blockIdx.z * sA;
    const float* Bm = Bb + (size_t)blockIdx.z * sB;
    float*       Cm = Cb + (size_t)blockIdx.z * sC;

    __shared__ unsigned As[2][BM * KP];
    __shared__ unsigned Bs[2][BN * KP];

    const int tid  = threadIdx.x;
    const int wid  = tid >> 5;
    const int lane = tid & 31;
    const int g    = lane >> 2;
    const int tig  = lane & 3;
    const int wm0  = (wid >> 2) * 64;
    const int wn0  = (wid & 3) * 32;

    float acc[4][4][4];
    #pragma unroll
    for (int i = 0; i < 4; i++)
        #pragma unroll
        for (int j = 0; j < 4; j++)
            #pragma unroll
            for (int r = 0; r < 4; r++) acc[i][j][r] = 0.f;

    const int lrow = tid >> 2;
    const int lkq  = (tid & 3) << 2;

    float4 ra[2], rb[2];

    auto ldAB = [&](int kt) {
        #pragma unroll
        for (int j = 0; j < 2; j++) {
            int m = lrow + j * 64;
            int gm = m0 + m;
            ra[j] = (gm < M) ? *(const float4*)(A + (size_t)gm * lda + kt * BKK + lkq)
                             : make_float4(0.f, 0.f, 0.f, 0.f);
            int gn = n0 + m;
            rb[j] = (gn < N) ? *(const float4*)(Bm + (size_t)gn * ldb + kt * BKK + lkq)
                             : make_float4(0.f, 0.f, 0.f, 0.f);
        }
    };
    auto stAB = [&](int buf) {
        #pragma unroll
        for (int j = 0; j < 2; j++) {
            int m = lrow + j * 64;
            unsigned* pa = &As[buf][m * KP + lkq];
            pa[0] = f2tf(ra[j].x); pa[1] = f2tf(ra[j].y);
            pa[2] = f2tf(ra[j].z); pa[3] = f2tf(ra[j].w);
            unsigned* pb = &Bs[buf][m * KP + lkq];
            pb[0] = f2tf(rb[j].x); pb[1] = f2tf(rb[j].y);
            pb[2] = f2tf(rb[j].z); pb[3] = f2tf(rb[j].w);
        }
    };

    const int nk = K / BKK;
    ldAB(0);
    stAB(0);
    __syncthreads();

    for (int kt = 0; kt < nk; kt++) {
        int buf = kt & 1;
        if (kt + 1 < nk) ldAB(kt + 1);

        #pragma unroll
        for (int kk = 0; kk < 2; kk++) {
            unsigned af[4][4], bf[4][2];
            #pragma unroll
            for (int ti = 0; ti < 4; ti++) {
                int r0 = (wm0 + ti * 16 + g) * KP + kk * 8 + tig;
                af[ti][0] = As[buf][r0];
                af[ti][1] = As[buf][r0 + 8 * KP];
                af[ti][2] = As[buf][r0 + 4];
                af[ti][3] = As[buf][r0 + 8 * KP + 4];
            }
            #pragma unroll
            for (int tj = 0; tj < 4; tj++) {
                int r0 = (wn0 + tj * 8 + g) * KP + kk * 8 + tig;
                bf[tj][0] = Bs[buf][r0];
                bf[tj][1] = Bs[buf][r0 + 4];
            }
            #pragma unroll
            for (int ti = 0; ti < 4; ti++)
                #pragma unroll
                for (int tj = 0; tj < 4; tj++)
                    mma_tf32(acc[ti][tj], af[ti], bf[tj]);
        }

        if (kt + 1 < nk) {
            stAB(buf ^ 1);
            __syncthreads();
        }
    }

    #pragma unroll
    for (int ti = 0; ti < 4; ti++) {
        int gm = m0 + wm0 + ti * 16 + g;
        #pragma unroll
        for (int tj = 0; tj < 4; tj++) {
            int gn = n0 + wn0 + tj * 8 + tig * 2;
            if (gn < N) {
                if (gm < M)
                    *(float2*)(Cm + (size_t)gm * ldc + gn) =
                        make_float2(acc[ti][tj][0], acc[ti][tj][1]);
                if (gm + 8 < M)
                    *(float2*)(Cm + (size_t)(gm + 8) * ldc + gn) =
                        make_float2(acc[ti][tj][2], acc[ti][tj][3]);
            }
        }
    }
}

// ---------------------------------------------------------------------------
// Fused flash attention (tf32 tensor cores, online softmax).
// Grid: x = b*H+h (32), y = Q tile (16, reversed for heavy-first scheduling).
// 256 threads = 8 warps; each warp owns 16 Q rows and the full tile width.
// Q tile 128x192 resident in smem; K/V tiles of 64 keys streamed.
// P (softmaxed probs) round-trips through per-warp-private smem region.
// ---------------------------------------------------------------------------
#define QP  196   // 192 + 4 pad (words): conflict-free fragment LDS
#define KP2 196
#define VP  68    // 64 + 4 pad
#define PP  68

#define FLASH_SMEM_WORDS (128*QP + 64*KP2 + 128*VP + 128*PP)   // 55040
#define FLASH_SMEM_BYTES (FLASH_SMEM_WORDS * 4)                // 220160

__global__ void __launch_bounds__(256, 1)
flash_attn(const float* __restrict__ qg, const float* __restrict__ kg,
           const float* __restrict__ vg, float* __restrict__ ao)
{
    extern __shared__ unsigned smx[];
    unsigned* Qs = smx;                  // [row][k]  128 x QP
    unsigned* Ks = Qs + 128*QP;          // [key][k]   64 x KP2
    unsigned* Vs = Ks + 64*KP2;          // [d][key]  128 x VP  (transposed)
    unsigned* Ps = Vs + 128*VP;          // [row][key] 128 x PP

    const int z  = blockIdx.x;                       // b*H + h
    const int iy = (int)gridDim.y - 1 - blockIdx.y;  // heavy tiles first
    const int q0 = iy * 128;
    const int b = z / H_, h = z % H_;

    const float* Qg = qg + (size_t)z * T_ * D_;
    const float* Kg = kg + (size_t)z * T_ * D_;
    const float* Vg = vg + (size_t)z * T_ * HS_;

    const int tid = threadIdx.x;
    const int wid = tid >> 5, lane = tid & 31;
    const int g = lane >> 2, tig = lane & 3;
    const int qrow0 = q0 + wid * 16 + g;   // this thread's row (and +8)

    // Load Q tile (128 x 192) -> tf32 smem
    #pragma unroll
    for (int it = 0; it < 24; it++) {
        int idx = tid + it * 256;
        int row = idx / 48, kq = (idx % 48) * 4;
        float4 v4 = *(const float4*)(Qg + (size_t)(q0 + row) * D_ + kq);
        unsigned* p = &Qs[row * QP + kq];
        p[0] = f2tf(v4.x); p[1] = f2tf(v4.y); p[2] = f2tf(v4.z); p[3] = f2tf(v4.w);
    }

    float m_i[2] = {-1e30f, -1e30f};
    float l_i[2] = {0.f, 0.f};
    float o[16][4];
    #pragma unroll
    for (int j = 0; j < 16; j++)
        #pragma unroll
        for (int r = 0; r < 4; r++) o[j][r] = 0.f;

    const int nkt = 2 * iy + 2;     // causal: tiles of 64 keys
    const float scale = 0.07216878364870323f;  // 1/sqrt(192)

    for (int kt = 0; kt < nkt; kt++) {
        __syncthreads();   // prev PV (and Q-tile fill) complete before refill

        // K tile 64 x 192
        #pragma unroll
        for (int it = 0; it < 12; it++) {
            int idx = tid + it * 256;
            int row = idx / 48, kq = (idx % 48) * 4;
            float4 v4 = *(const float4*)(Kg + (size_t)(kt * 64 + row) * D_ + kq);
            unsigned* p = &Ks[row * KP2 + kq];
            p[0] = f2tf(v4.x); p[1] = f2tf(v4.y); p[2] = f2tf(v4.z); p[3] = f2tf(v4.w);
        }
        // V tile 64 x 128, stored transposed [d][key]
        #pragma unroll
        for (int it = 0; it < 8; it++) {
            int idx = tid + it * 256;
            int kp = idx / 32, dq = (idx % 32) * 4;
            float4 v4 = *(const float4*)(Vg + (size_t)(kt * 64 + kp) * HS_ + dq);
            Vs[(dq + 0) * VP + kp] = f2tf(v4.x);
            Vs[(dq + 1) * VP + kp] = f2tf(v4.y);
            Vs[(dq + 2) * VP + kp] = f2tf(v4.z);
            Vs[(dq + 3) * VP + kp] = f2tf(v4.w);
        }
        __syncthreads();

        // S = Q K^T : warp tile m16 x n64, k = 192
        float s[8][4];
        #pragma unroll
        for (int j = 0; j < 8; j++)
            #pragma unroll
            for (int r = 0; r < 4; r++) s[j][r] = 0.f;

        #pragma unroll
        for (int kk = 0; kk < 24; kk++) {
            unsigned a[4];
            int r0 = (wid * 16 + g) * QP + kk * 8 + tig;
            a[0] = Qs[r0];          a[1] = Qs[r0 + 8 * QP];
            a[2] = Qs[r0 + 4];      a[3] = Qs[r0 + 8 * QP + 4];
            #pragma unroll
            for (int j = 0; j < 8; j++) {
                unsigned bq[2];
                int rb = (j * 8 + g) * KP2 + kk * 8 + tig;
                bq[0] = Ks[rb]; bq[1] = Ks[rb + 4];
                mma_tf32(s[j], a, bq);
            }
        }

        // Online softmax (rows g and g+8 of the warp's m16 tile)
        const bool diag = (kt >= 2 * iy);   // only last two tiles touch diagonal
        #pragma unroll
        for (int r2 = 0; r2 < 2; r2++) {
            const int row = qrow0 + r2 * 8;
            float mx = -1e30f;
            #pragma unroll
            for (int j = 0; j < 8; j++) {
                #pragma unroll
                for (int c = 0; c < 2; c++) {
                    int r = r2 * 2 + c;
                    float v = s[j][r] * scale;
                    if (diag) {
                        int col = kt * 64 + j * 8 + 2 * tig + c;
                        if (col > row) v = -1e30f;
                    }
                    s[j][r] = v;
                    mx = fmaxf(mx, v);
                }
            }
            mx = fmaxf(mx, __shfl_xor_sync(0xffffffffu, mx, 1));
            mx = fmaxf(mx, __shfl_xor_sync(0xffffffffu, mx, 2));
            float mnew = fmaxf(m_i[r2], mx);
            float alpha = __expf(m_i[r2] - mnew);
            m_i[r2] = mnew;

            float ls = 0.f;
            #pragma unroll
            for (int j = 0; j < 8; j++) {
                #pragma unroll
                for (int c = 0; c < 2; c++) {
                    int r = r2 * 2 + c;
                    float p = __expf(s[j][r] - mnew);
                    s[j][r] = p;
                    ls += p;
                }
            }
            ls += __shfl_xor_sync(0xffffffffu, ls, 1);
            ls += __shfl_xor_sync(0xffffffffu, ls, 2);
            l_i[r2] = l_i[r2] * alpha + ls;

            #pragma unroll
            for (int j = 0; j < 16; j++) {
                o[j][r2 * 2 + 0] *= alpha;
                o[j][r2 * 2 + 1] *= alpha;
            }
        }

        // P -> smem (per-warp-private rows; acc layout -> A-fragment layout)
        {
            int base0 = (wid * 16 + g) * PP;
            int base1 = (wid * 16 + g + 8) * PP;
            #pragma unroll
            for (int j = 0; j < 8; j++) {
                int cc = j * 8 + 2 * tig;
                Ps[base0 + cc    ] = f2tf(s[j][0]);
                Ps[base0 + cc + 1] = f2tf(s[j][1]);
                Ps[base1 + cc    ] = f2tf(s[j][2]);
                Ps[base1 + cc + 1] = f2tf(s[j][3]);
            }
        }
        __syncwarp();

        // O += P V : warp tile m16 x n128, k = 64
        #pragma unroll
        for (int kk = 0; kk < 8; kk++) {
            unsigned a[4];
            int r0 = (wid * 16 + g) * PP + kk * 8 + tig;
            a[0] = Ps[r0];          a[1] = Ps[r0 + 8 * PP];
            a[2] = Ps[r0 + 4];      a[3] = Ps[r0 + 8 * PP + 4];
            #pragma unroll
            for (int j = 0; j < 16; j++) {
                unsigned bq[2];
                int rb = (j * 8 + g) * VP + kk * 8 + tig;
                bq[0] = Vs[rb]; bq[1] = Vs[rb + 4];
                mma_tf32(o[j], a, bq);
            }
        }
    }

    // Epilogue: normalize and scatter into (b, t, h*HS + d)
    const float inv0 = 1.f / l_i[0];
    const float inv1 = 1.f / l_i[1];
    #pragma unroll
    for (int j = 0; j < 16; j++) {
        int d = j * 8 + 2 * tig;
        size_t base0 = ((size_t)(b * T_ + qrow0    )) * C_ + h * HS_ + d;
        size_t base1 = ((size_t)(b * T_ + qrow0 + 8)) * C_ + h * HS_ + d;
        *(float2*)(ao + base0) = make_float2(o[j][0] * inv0, o[j][1] * inv0);
        *(float2*)(ao + base1) = make_float2(o[j][2] * inv1, o[j][3] * inv1);
    }
}

// ---------------------------------------------------------------------------
// Pack + RoPE kernels
// ---------------------------------------------------------------------------
__global__ void pack_q(const float* __restrict__ qc, const float* __restrict__ qr,
                       const float* __restrict__ cs, const float* __restrict__ sn,
                       float* __restrict__ q)
{
    int idx = blockIdx.x * blockDim.x + threadIdx.x;
    if (idx >= B_*H_*T_*D_) return;
    int d = idx % D_;
    int t = (idx / D_) % T_;
    int h = (idx / (D_*T_)) % H_;
    int b = idx / (D_*T_*H_);
    float val;
    if (d < HS_) {
        val = qc[((size_t)(b*T_ + t))*C_ + h*HS_ + d];
    } else {
        int j = d - HS_;
        int p = j >> 1;
        const float* base = qr + ((size_t)(b*T_ + t))*(H_*RHD_) + h*RHD_ + 2*p;
        float re = base[0], im = base[1];
        float c = cs[t*(RHD_/2) + p], s = sn[t*(RHD_/2) + p];
        val = (j & 1) ? (re*s + im*c) : (re*c - im*s);
    }
    q[idx] = val;
}

__global__ void pack_k(const float* __restrict__ kc, const float* __restrict__ kr,
                       const float* __restrict__ cs, const float* __restrict__ sn,
                       float* __restrict__ k)
{
    int idx = blockIdx.x * blockDim.x + threadIdx.x;
    if (idx >= B_*H_*T_*D_) return;
    int d = idx % D_;
    int t = (idx / D_) % T_;
    int h = (idx / (D_*T_)) % H_;
    int b = idx / (D_*T_*H_);
    float val;
    if (d < HS_) {
        val = kc[((size_t)(b*T_ + t))*C_ + h*HS_ + d];
    } else {
        int j = d - HS_;
        int p = j >> 1;
        const float* base = kr + ((size_t)(b*T_ + t))*RHD_ + 2*p;
        float re = base[0], im = base[1];
        float c = cs[t*(RHD_/2) + p], s = sn[t*(RHD_/2) + p];
        val = (j & 1) ? (re*s + im*c) : (re*c - im*s);
    }
    k[idx] = val;
}

__global__ void pack_v(const float* __restrict__ vt, float* __restrict__ v)
{
    int idx = blockIdx.x * blockDim.x + threadIdx.x;
    if (idx >= B_*H_*T_*HS_) return;
    int d = idx % HS_;
    int t = (idx / HS_) % T_;
    int h = (idx / (HS_*T_)) % H_;
    int b = idx / (HS_*T_*H_);
    v[idx] = vt[((size_t)(b*T_ + t))*C_ + h*HS_ + d];
}

// ---------------------------------------------------------------------------
// Launch
// ---------------------------------------------------------------------------
extern "C" void kernel_launch(void* const* d_in, const int* in_sizes, int n_in,
                              void* d_out, int out_size)
{
    const float* x    = (const float*)d_in[0];
    const float* fc   = (const float*)d_in[1];
    const float* fs   = (const float*)d_in[2];
    const float* Wdq  = (const float*)d_in[3];
    const float* Wuq  = (const float*)d_in[4];
    const float* Wdkv = (const float*)d_in[5];
    const float* Wuk  = (const float*)d_in[6];
    const float* Wuv  = (const float*)d_in[7];
    const float* Wqr  = (const float*)d_in[8];
    const float* Wkr  = (const float*)d_in[9];
    const float* Wo   = (const float*)d_in[10];
    float* out = (float*)d_out;

    float *cq, *ckv, *qc, *kc, *vt, *qr, *kr, *q, *k, *v, *ao;
    cudaGetSymbolAddress((void**)&cq,  g_cq);
    cudaGetSymbolAddress((void**)&ckv, g_ckv);
    cudaGetSymbolAddress((void**)&qc,  g_qc);
    cudaGetSymbolAddress((void**)&kc,  g_kc);
    cudaGetSymbolAddress((void**)&vt,  g_vt);
    cudaGetSymbolAddress((void**)&qr,  g_qr);
    cudaGetSymbolAddress((void**)&kr,  g_kr);
    cudaGetSymbolAddress((void**)&q,   g_q);
    cudaGetSymbolAddress((void**)&k,   g_k);
    cudaGetSymbolAddress((void**)&v,   g_v);
    cudaGetSymbolAddress((void**)&ao,  g_ao);

    static bool attr_set = false;
    if (!attr_set) {
        cudaFuncSetAttribute(flash_attn, cudaFuncAttributeMaxDynamicSharedMemorySize,
                             FLASH_SMEM_BYTES);
        attr_set = true;
    }

    const int M = B_ * T_;   // 4096
    dim3 blk(256);
    auto grd = [](int m, int n) { return dim3((n+127)/128, (m+127)/128, 1); };

    // Projections (NT, tf32 tensor cores)
    mma_gemm_nt<false><<<grd(M, NLQ_),   blk>>>(x,   Wdq,  cq, M, NLQ_,    C_,   C_,   C_,   NLQ_,    0,0,0);
    mma_gemm_nt<false><<<grd(M, NLKV_),  blk>>>(x,   Wdkv, ckv,M, NLKV_,   C_,   C_,   C_,   NLKV_,   0,0,0);
    mma_gemm_nt<false><<<grd(M, RHD_),   blk>>>(x,   Wkr,  kr, M, RHD_,    C_,   C_,   C_,   RHD_,    0,0,0);
    mma_gemm_nt<false><<<grd(M, C_),     blk>>>(cq,  Wuq,  qc, M, C_,      NLQ_, NLQ_, NLQ_, C_,      0,0,0);
    mma_gemm_nt<false><<<grd(M, H_*RHD_),blk>>>(cq,  Wqr,  qr, M, H_*RHD_, NLQ_, NLQ_, NLQ_, H_*RHD_, 0,0,0);
    mma_gemm_nt<false><<<grd(M, C_),     blk>>>(ckv, Wuk,  kc, M, C_,      NLKV_,NLKV_,NLKV_,C_,      0,0,0);
    mma_gemm_nt<false><<<grd(M, C_),     blk>>>(ckv, Wuv,  vt, M, C_,      NLKV_,NLKV_,NLKV_,C_,      0,0,0);

    // RoPE + concat + layout packs
    pack_q<<<(B_*H_*T_*D_  + 255)/256, 256>>>(qc, qr, fc, fs, q);
    pack_k<<<(B_*H_*T_*D_  + 255)/256, 256>>>(kc, kr, fc, fs, k);
    pack_v<<<(B_*H_*T_*HS_ + 255)/256, 256>>>(vt, v);

    // Fused flash attention (scores + softmax + attn@V)
    dim3 gfa(B_ * H_, T_ / 128);
    flash_attn<<<gfa, blk, FLASH_SMEM_BYTES>>>(q, k, v, ao);

    // Output projection
    mma_gemm_nt<false><<<grd(M, C_), blk>>>(ao, Wo, out, M, C_, C_, C_, C_, C_, 0,0,0);
}

// round 5
// speedup vs baseline: 3.5294x; 1.1755x over previous
#include <cuda_runtime.h>
#include <math.h>

#define B_   2
#define T_   2048
#define C_   2048
#define H_   16
#define HS_  128
#define NLQ_ 512
#define NLKV_ 512
#define RHD_ 64
#define D_   192

__device__ float g_cq [B_*T_*NLQ_];
__device__ float g_ckv[B_*T_*NLKV_];
__device__ float g_q  [B_*H_*T_*D_];
__device__ float g_k  [B_*H_*T_*D_];
__device__ float g_v  [B_*H_*T_*HS_];
__device__ float g_ao [B_*T_*C_];

__device__ __forceinline__ unsigned f2tf(float f) {
    unsigned u;
    asm("cvt.rna.tf32.f32 %0, %1;" : "=r"(u) : "f"(f));
    return u;
}
__device__ __forceinline__ void mma_tf32(float* d, const unsigned* a, const unsigned* b) {
    asm volatile(
        "mma.sync.aligned.m16n8k8.row.col.f32.tf32.tf32.f32 "
        "{%0,%1,%2,%3}, {%4,%5,%6,%7}, {%8,%9}, {%0,%1,%2,%3};"
        : "+f"(d[0]), "+f"(d[1]), "+f"(d[2]), "+f"(d[3])
        : "r"(a[0]), "r"(a[1]), "r"(a[2]), "r"(a[3]), "r"(b[0]), "r"(b[1]));
}
__device__ __forceinline__ void cp16(float* dst, const float* src, bool valid) {
    unsigned d = (unsigned)__cvta_generic_to_shared(dst);
    int sz = valid ? 16 : 0;
    asm volatile("cp.async.cg.shared.global [%0], [%1], 16, %2;\n"
                 :: "r"(d), "l"(src), "r"(sz) : "memory");
}

// ---------------------------------------------------------------------------
// 4-stage cp.async pipelined tf32 GEMM, NT: C[m,n] = sum_k A[m,k]*B[n,k]
// M fixed = 4096 (b*T+t). 128 threads, 4 warps (2x2), warp tile 64x64.
// MODE 0: C[gm*ldc+gn]
// MODE 1: head scatter: gn=h*HS+d -> C[((b*H+h)*T+t)*ldc + d]
// MODE 3: q_r rope:     gn=h*64+j -> g_q[((b*H+h)*T+t)*192 + 128+j]
// MODE 4: k_r rope bcast: gn=j(<64) -> g_k[((b*H+h)*T+t)*192 + 128+j], all h
// ---------------------------------------------------------------------------
#define GEMM_SMEM_BYTES (8 * 2560 * 4)   // 81920

template<int MODE>
__global__ void __launch_bounds__(128, 2)
gemm_cp(const float* __restrict__ A, const float* __restrict__ Bw,
        float* __restrict__ Cout, int N, int K, int lda, int ldb, int ldc,
        const float* __restrict__ fc, const float* __restrict__ fs)
{
    extern __shared__ float gsm[];
    float* As = gsm;             // 4 stages x 128 x 20
    float* Bs = gsm + 4 * 2560;

    const int m0 = blockIdx.y * 128;
    const int n0 = blockIdx.x * 128;
    const int tid  = threadIdx.x;
    const int wid  = tid >> 5;
    const int lane = tid & 31;
    const int g    = lane >> 2;
    const int tig  = lane & 3;
    const int wr   = (wid >> 1) * 64;
    const int wc   = (wid & 1) * 64;
    const int lrow = tid >> 2;
    const int lkq  = (tid & 3) * 4;
    const int nk   = K / 16;

    float acc[4][8][4];
    #pragma unroll
    for (int i = 0; i < 4; i++)
        #pragma unroll
        for (int j = 0; j < 8; j++)
            #pragma unroll
            for (int r = 0; r < 4; r++) acc[i][j][r] = 0.f;

    auto issue = [&](int kt) {
        int s = kt & 3;
        #pragma unroll
        for (int i = 0; i < 4; i++) {
            int r = lrow + i * 32;
            cp16(As + s * 2560 + r * 20 + lkq,
                 A + (size_t)(m0 + r) * lda + kt * 16 + lkq, true);
            cp16(Bs + s * 2560 + r * 20 + lkq,
                 Bw + (size_t)(n0 + r) * ldb + kt * 16 + lkq, (n0 + r) < N);
        }
        asm volatile("cp.async.commit_group;\n" ::: "memory");
    };

    issue(0); issue(1); issue(2);
    asm volatile("cp.async.wait_group 2;\n" ::: "memory");
    __syncthreads();

    for (int kt = 0; kt < nk; kt++) {
        if (kt + 3 < nk) issue(kt + 3);
        else asm volatile("cp.async.commit_group;\n" ::: "memory");

        const float* Ab = As + (kt & 3) * 2560;
        const float* Bb = Bs + (kt & 3) * 2560;
        #pragma unroll
        for (int kk = 0; kk < 2; kk++) {
            unsigned af[4][4], bf[8][2];
            #pragma unroll
            for (int ti = 0; ti < 4; ti++) {
                int r0 = (wr + ti * 16 + g) * 20 + kk * 8 + tig;
                af[ti][0] = f2tf(Ab[r0]);
                af[ti][1] = f2tf(Ab[r0 + 160]);
                af[ti][2] = f2tf(Ab[r0 + 4]);
                af[ti][3] = f2tf(Ab[r0 + 164]);
            }
            #pragma unroll
            for (int tj = 0; tj < 8; tj++) {
                int r0 = (wc + tj * 8 + g) * 20 + kk * 8 + tig;
                bf[tj][0] = f2tf(Bb[r0]);
                bf[tj][1] = f2tf(Bb[r0 + 4]);
            }
            #pragma unroll
            for (int ti = 0; ti < 4; ti++)
                #pragma unroll
                for (int tj = 0; tj < 8; tj++)
                    mma_tf32(acc[ti][tj], af[ti], bf[tj]);
        }
        asm volatile("cp.async.wait_group 2;\n" ::: "memory");
        __syncthreads();
    }

    #pragma unroll
    for (int ti = 0; ti < 4; ti++) {
        #pragma unroll
        for (int rh = 0; rh < 2; rh++) {
            int gm = m0 + wr + ti * 16 + g + rh * 8;
            int bb = gm >> 11;
            int tt = gm & (T_ - 1);
            #pragma unroll
            for (int tj = 0; tj < 8; tj++) {
                int gn = n0 + wc + tj * 8 + tig * 2;
                float v0 = acc[ti][tj][rh * 2 + 0];
                float v1 = acc[ti][tj][rh * 2 + 1];
                if (MODE == 0) {
                    if (gn < N)
                        *(float2*)(Cout + (size_t)gm * ldc + gn) = make_float2(v0, v1);
                } else if (MODE == 1) {
                    int hh = gn >> 7, dd = gn & 127;
                    *(float2*)(Cout + ((size_t)(bb * H_ + hh) * T_ + tt) * ldc + dd) =
                        make_float2(v0, v1);
                } else if (MODE == 3) {
                    int hh = gn >> 6, jj = gn & 63;
                    int p = jj >> 1;
                    float c = fc[tt * 32 + p], s = fs[tt * 32 + p];
                    *(float2*)(Cout + ((size_t)(bb * H_ + hh) * T_ + tt) * D_ + HS_ + jj) =
                        make_float2(v0 * c - v1 * s, v0 * s + v1 * c);
                } else if (MODE == 4) {
                    if (gn < N) {
                        int p = gn >> 1;
                        float c = fc[tt * 32 + p], s = fs[tt * 32 + p];
                        float o0 = v0 * c - v1 * s;
                        float o1 = v0 * s + v1 * c;
                        #pragma unroll
                        for (int hh = 0; hh < H_; hh++)
                            *(float2*)(Cout + ((size_t)(bb * H_ + hh) * T_ + tt) * D_ + HS_ + gn) =
                                make_float2(o0, o1);
                    }
                }
            }
        }
    }
}

// ---------------------------------------------------------------------------
// Fused flash attention (unchanged from R3)
// ---------------------------------------------------------------------------
#define QP  196
#define KP2 196
#define VP  68
#define PP  68
#define FLASH_SMEM_WORDS (128*QP + 64*KP2 + 128*VP + 128*PP)
#define FLASH_SMEM_BYTES (FLASH_SMEM_WORDS * 4)

__global__ void __launch_bounds__(256, 1)
flash_attn(const float* __restrict__ qg, const float* __restrict__ kg,
           const float* __restrict__ vg, float* __restrict__ ao)
{
    extern __shared__ unsigned smx[];
    unsigned* Qs = smx;
    unsigned* Ks = Qs + 128*QP;
    unsigned* Vs = Ks + 64*KP2;
    unsigned* Ps = Vs + 128*VP;

    const int z  = blockIdx.x;
    const int iy = (int)gridDim.y - 1 - blockIdx.y;
    const int q0 = iy * 128;
    const int b = z / H_, h = z % H_;

    const float* Qg = qg + (size_t)z * T_ * D_;
    const float* Kg = kg + (size_t)z * T_ * D_;
    const float* Vg = vg + (size_t)z * T_ * HS_;

    const int tid = threadIdx.x;
    const int wid = tid >> 5, lane = tid & 31;
    const int g = lane >> 2, tig = lane & 3;
    const int qrow0 = q0 + wid * 16 + g;

    #pragma unroll
    for (int it = 0; it < 24; it++) {
        int idx = tid + it * 256;
        int row = idx / 48, kq = (idx % 48) * 4;
        float4 v4 = *(const float4*)(Qg + (size_t)(q0 + row) * D_ + kq);
        unsigned* p = &Qs[row * QP + kq];
        p[0] = f2tf(v4.x); p[1] = f2tf(v4.y); p[2] = f2tf(v4.z); p[3] = f2tf(v4.w);
    }

    float m_i[2] = {-1e30f, -1e30f};
    float l_i[2] = {0.f, 0.f};
    float o[16][4];
    #pragma unroll
    for (int j = 0; j < 16; j++)
        #pragma unroll
        for (int r = 0; r < 4; r++) o[j][r] = 0.f;

    const int nkt = 2 * iy + 2;
    const float scale = 0.07216878364870323f;

    for (int kt = 0; kt < nkt; kt++) {
        __syncthreads();
        #pragma unroll
        for (int it = 0; it < 12; it++) {
            int idx = tid + it * 256;
            int row = idx / 48, kq = (idx % 48) * 4;
            float4 v4 = *(const float4*)(Kg + (size_t)(kt * 64 + row) * D_ + kq);
            unsigned* p = &Ks[row * KP2 + kq];
            p[0] = f2tf(v4.x); p[1] = f2tf(v4.y); p[2] = f2tf(v4.z); p[3] = f2tf(v4.w);
        }
        #pragma unroll
        for (int it = 0; it < 8; it++) {
            int idx = tid + it * 256;
            int kp = idx / 32, dq = (idx % 32) * 4;
            float4 v4 = *(const float4*)(Vg + (size_t)(kt * 64 + kp) * HS_ + dq);
            Vs[(dq + 0) * VP + kp] = f2tf(v4.x);
            Vs[(dq + 1) * VP + kp] = f2tf(v4.y);
            Vs[(dq + 2) * VP + kp] = f2tf(v4.z);
            Vs[(dq + 3) * VP + kp] = f2tf(v4.w);
        }
        __syncthreads();

        float s[8][4];
        #pragma unroll
        for (int j = 0; j < 8; j++)
            #pragma unroll
            for (int r = 0; r < 4; r++) s[j][r] = 0.f;

        #pragma unroll
        for (int kk = 0; kk < 24; kk++) {
            unsigned a[4];
            int r0 = (wid * 16 + g) * QP + kk * 8 + tig;
            a[0] = Qs[r0];          a[1] = Qs[r0 + 8 * QP];
            a[2] = Qs[r0 + 4];      a[3] = Qs[r0 + 8 * QP + 4];
            #pragma unroll
            for (int j = 0; j < 8; j++) {
                unsigned bq[2];
                int rb = (j * 8 + g) * KP2 + kk * 8 + tig;
                bq[0] = Ks[rb]; bq[1] = Ks[rb + 4];
                mma_tf32(s[j], a, bq);
            }
        }

        const bool diag = (kt >= 2 * iy);
        #pragma unroll
        for (int r2 = 0; r2 < 2; r2++) {
            const int row = qrow0 + r2 * 8;
            float mx = -1e30f;
            #pragma unroll
            for (int j = 0; j < 8; j++) {
                #pragma unroll
                for (int c = 0; c < 2; c++) {
                    int r = r2 * 2 + c;
                    float v = s[j][r] * scale;
                    if (diag) {
                        int col = kt * 64 + j * 8 + 2 * tig + c;
                        if (col > row) v = -1e30f;
                    }
                    s[j][r] = v;
                    mx = fmaxf(mx, v);
                }
            }
            mx = fmaxf(mx, __shfl_xor_sync(0xffffffffu, mx, 1));
            mx = fmaxf(mx, __shfl_xor_sync(0xffffffffu, mx, 2));
            float mnew = fmaxf(m_i[r2], mx);
            float alpha = __expf(m_i[r2] - mnew);
            m_i[r2] = mnew;

            float ls = 0.f;
            #pragma unroll
            for (int j = 0; j < 8; j++) {
                #pragma unroll
                for (int c = 0; c < 2; c++) {
                    int r = r2 * 2 + c;
                    float p = __expf(s[j][r] - mnew);
                    s[j][r] = p;
                    ls += p;
                }
            }
            ls += __shfl_xor_sync(0xffffffffu, ls, 1);
            ls += __shfl_xor_sync(0xffffffffu, ls, 2);
            l_i[r2] = l_i[r2] * alpha + ls;

            #pragma unroll
            for (int j = 0; j < 16; j++) {
                o[j][r2 * 2 + 0] *= alpha;
                o[j][r2 * 2 + 1] *= alpha;
            }
        }

        {
            int base0 = (wid * 16 + g) * PP;
            int base1 = (wid * 16 + g + 8) * PP;
            #pragma unroll
            for (int j = 0; j < 8; j++) {
                int cc = j * 8 + 2 * tig;
                Ps[base0 + cc    ] = f2tf(s[j][0]);
                Ps[base0 + cc + 1] = f2tf(s[j][1]);
                Ps[base1 + cc    ] = f2tf(s[j][2]);
                Ps[base1 + cc + 1] = f2tf(s[j][3]);
            }
        }
        __syncwarp();

        #pragma unroll
        for (int kk = 0; kk < 8; kk++) {
            unsigned a[4];
            int r0 = (wid * 16 + g) * PP + kk * 8 + tig;
            a[0] = Ps[r0];          a[1] = Ps[r0 + 8 * PP];
            a[2] = Ps[r0 + 4];      a[3] = Ps[r0 + 8 * PP + 4];
            #pragma unroll
            for (int j = 0; j < 16; j++) {
                unsigned bq[2];
                int rb = (j * 8 + g) * VP + kk * 8 + tig;
                bq[0] = Vs[rb]; bq[1] = Vs[rb + 4];
                mma_tf32(o[j], a, bq);
            }
        }
    }

    const float inv0 = 1.f / l_i[0];
    const float inv1 = 1.f / l_i[1];
    #pragma unroll
    for (int j = 0; j < 16; j++) {
        int d = j * 8 + 2 * tig;
        size_t base0 = ((size_t)(b * T_ + qrow0    )) * C_ + h * HS_ + d;
        size_t base1 = ((size_t)(b * T_ + qrow0 + 8)) * C_ + h * HS_ + d;
        *(float2*)(ao + base0) = make_float2(o[j][0] * inv0, o[j][1] * inv0);
        *(float2*)(ao + base1) = make_float2(o[j][2] * inv1, o[j][3] * inv1);
    }
}

// ---------------------------------------------------------------------------
// Launch
// ---------------------------------------------------------------------------
extern "C" void kernel_launch(void* const* d_in, const int* in_sizes, int n_in,
                              void* d_out, int out_size)
{
    const float* x    = (const float*)d_in[0];
    const float* fc   = (const float*)d_in[1];
    const float* fs   = (const float*)d_in[2];
    const float* Wdq  = (const float*)d_in[3];
    const float* Wuq  = (const float*)d_in[4];
    const float* Wdkv = (const float*)d_in[5];
    const float* Wuk  = (const float*)d_in[6];
    const float* Wuv  = (const float*)d_in[7];
    const float* Wqr  = (const float*)d_in[8];
    const float* Wkr  = (const float*)d_in[9];
    const float* Wo   = (const float*)d_in[10];
    float* out = (float*)d_out;

    float *cq, *ckv, *q, *k, *v, *ao;
    cudaGetSymbolAddress((void**)&cq,  g_cq);
    cudaGetSymbolAddress((void**)&ckv, g_ckv);
    cudaGetSymbolAddress((void**)&q,   g_q);
    cudaGetSymbolAddress((void**)&k,   g_k);
    cudaGetSymbolAddress((void**)&v,   g_v);
    cudaGetSymbolAddress((void**)&ao,  g_ao);

    static bool attr_set = false;
    if (!attr_set) {
        cudaFuncSetAttribute(flash_attn, cudaFuncAttributeMaxDynamicSharedMemorySize,
                             FLASH_SMEM_BYTES);
        cudaFuncSetAttribute(gemm_cp<0>, cudaFuncAttributeMaxDynamicSharedMemorySize,
                             GEMM_SMEM_BYTES);
        cudaFuncSetAttribute(gemm_cp<1>, cudaFuncAttributeMaxDynamicSharedMemorySize,
                             GEMM_SMEM_BYTES);
        cudaFuncSetAttribute(gemm_cp<3>, cudaFuncAttributeMaxDynamicSharedMemorySize,
                             GEMM_SMEM_BYTES);
        cudaFuncSetAttribute(gemm_cp<4>, cudaFuncAttributeMaxDynamicSharedMemorySize,
                             GEMM_SMEM_BYTES);
        attr_set = true;
    }

    dim3 blk(128);
    auto grd = [](int n) { return dim3((n + 127) / 128, 32, 1); };  // M=4096 fixed

    // Down projections
    gemm_cp<0><<<grd(NLQ_),  blk, GEMM_SMEM_BYTES>>>(x, Wdq,  cq,  NLQ_,  C_, C_, C_, NLQ_,  fc, fs);
    gemm_cp<0><<<grd(NLKV_), blk, GEMM_SMEM_BYTES>>>(x, Wdkv, ckv, NLKV_, C_, C_, C_, NLKV_, fc, fs);
    // k_r: rope + broadcast into g_k[...,128:192]
    gemm_cp<4><<<grd(RHD_),  blk, GEMM_SMEM_BYTES>>>(x, Wkr,  k,   RHD_,  C_, C_, C_, 0,     fc, fs);
    // Up projections with fused scatter / rope epilogues
    gemm_cp<1><<<grd(C_),      blk, GEMM_SMEM_BYTES>>>(cq,  Wuq, q, C_,      NLQ_,  NLQ_,  NLQ_,  D_,  fc, fs);
    gemm_cp<3><<<grd(H_*RHD_), blk, GEMM_SMEM_BYTES>>>(cq,  Wqr, q, H_*RHD_, NLQ_,  NLQ_,  NLQ_,  0,   fc, fs);
    gemm_cp<1><<<grd(C_),      blk, GEMM_SMEM_BYTES>>>(ckv, Wuk, k, C_,      NLKV_, NLKV_, NLKV_, D_,  fc, fs);
    gemm_cp<1><<<grd(C_),      blk, GEMM_SMEM_BYTES>>>(ckv, Wuv, v, C_,      NLKV_, NLKV_, NLKV_, HS_, fc, fs);

    // Fused flash attention
    dim3 gfa(B_ * H_, T_ / 128);
    flash_attn<<<gfa, 256, FLASH_SMEM_BYTES>>>(q, k, v, ao);

    // Output projection
    gemm_cp<0><<<grd(C_), blk, GEMM_SMEM_BYTES>>>(ao, Wo, out, C_, C_, C_, C_, C_, fc, fs);
}

// round 6
// speedup vs baseline: 4.2477x; 1.2035x over previous
#include <cuda_runtime.h>
#include <math.h>

#define B_   2
#define T_   2048
#define C_   2048
#define H_   16
#define HS_  128
#define NLQ_ 512
#define NLKV_ 512
#define RHD_ 64
#define D_   192

__device__ float g_cq [B_*T_*NLQ_];
__device__ float g_ckv[B_*T_*NLKV_];
__device__ float g_q  [B_*H_*T_*D_];
__device__ float g_k  [B_*H_*T_*D_];
__device__ float g_v  [B_*H_*T_*HS_];
__device__ float g_ao [B_*T_*C_];

__device__ __forceinline__ unsigned f2tf(float f) {
    unsigned u;
    asm("cvt.rna.tf32.f32 %0, %1;" : "=r"(u) : "f"(f));
    return u;
}
__device__ __forceinline__ void mma_tf32(float* d, const unsigned* a, const unsigned* b) {
    asm volatile(
        "mma.sync.aligned.m16n8k8.row.col.f32.tf32.tf32.f32 "
        "{%0,%1,%2,%3}, {%4,%5,%6,%7}, {%8,%9}, {%0,%1,%2,%3};"
        : "+f"(d[0]), "+f"(d[1]), "+f"(d[2]), "+f"(d[3])
        : "r"(a[0]), "r"(a[1]), "r"(a[2]), "r"(a[3]), "r"(b[0]), "r"(b[1]));
}
__device__ __forceinline__ void cp16(float* dst, const float* src, bool valid) {
    unsigned d = (unsigned)__cvta_generic_to_shared(dst);
    int sz = valid ? 16 : 0;
    asm volatile("cp.async.cg.shared.global [%0], [%1], 16, %2;\n"
                 :: "r"(d), "l"(src), "r"(sz) : "memory");
}

// ---------------------------------------------------------------------------
// 4-stage cp.async tf32 GEMM, NT. 256 threads, 8 warps (2m x 4n), warp 64x32.
// M fixed = 4096 (gm = b*T+t). B side reads from up to 3 row-concatenated
// weight matrices (B0|B1|B2 split at nb1/nb2), all with the same ldb.
// MODE 0: plain Cout[gm*ldc+gn]
// MODE 5: x-proj:  gn<512 -> g_cq ; <1024 -> g_ckv ; <1088 -> rope k_r bcast
// MODE 6: cq-proj: gn<2048 -> g_q head-scatter ; else rope q_r into g_q
// MODE 7: ckv-proj: gn<2048 -> g_k head-scatter ; else -> g_v head-scatter
// ---------------------------------------------------------------------------
#define GEMM_SMEM_BYTES (8 * 2560 * 4)   // 81920

template<int MODE>
__global__ void __launch_bounds__(256, 2)
gemm8(const float* __restrict__ A,
      const float* __restrict__ B0, const float* __restrict__ B1,
      const float* __restrict__ B2, int nb1, int nb2,
      int N, int K, int lda, int ldb,
      float* __restrict__ Cout, int ldc,
      const float* __restrict__ fc, const float* __restrict__ fs)
{
    extern __shared__ float gsm[];
    float* As = gsm;             // 4 stages x 128 x 20
    float* Bs = gsm + 4 * 2560;

    const int m0 = blockIdx.y * 128;
    const int n0 = blockIdx.x * 128;
    const int tid  = threadIdx.x;
    const int wid  = tid >> 5;
    const int lane = tid & 31;
    const int g    = lane >> 2;
    const int tig  = lane & 3;
    const int wr   = (wid >> 2) * 64;
    const int wc   = (wid & 3) * 32;
    const int lrow = tid >> 2;          // 0..63
    const int lkq  = (tid & 3) * 4;
    const int nk   = K / 16;

    float acc[4][4][4];
    #pragma unroll
    for (int i = 0; i < 4; i++)
        #pragma unroll
        for (int j = 0; j < 4; j++)
            #pragma unroll
            for (int r = 0; r < 4; r++) acc[i][j][r] = 0.f;

    auto issue = [&](int kt) {
        int s = kt & 3;
        #pragma unroll
        for (int i = 0; i < 2; i++) {
            int r = lrow + i * 64;
            cp16(As + s * 2560 + r * 20 + lkq,
                 A + (size_t)(m0 + r) * lda + kt * 16 + lkq, true);
            int br = n0 + r;
            const float* bp = (br < nb1) ? B0 + (size_t)br * ldb
                            : (br < nb2) ? B1 + (size_t)(br - nb1) * ldb
                                         : B2 + (size_t)(br - nb2) * ldb;
            cp16(Bs + s * 2560 + r * 20 + lkq, bp + kt * 16 + lkq, br < N);
        }
        asm volatile("cp.async.commit_group;\n" ::: "memory");
    };

    issue(0); issue(1); issue(2);
    asm volatile("cp.async.wait_group 2;\n" ::: "memory");
    __syncthreads();

    for (int kt = 0; kt < nk; kt++) {
        if (kt + 3 < nk) issue(kt + 3);
        else asm volatile("cp.async.commit_group;\n" ::: "memory");

        const float* Ab = As + (kt & 3) * 2560;
        const float* Bb = Bs + (kt & 3) * 2560;
        #pragma unroll
        for (int kk = 0; kk < 2; kk++) {
            unsigned af[4][4], bf[4][2];
            #pragma unroll
            for (int ti = 0; ti < 4; ti++) {
                int r0 = (wr + ti * 16 + g) * 20 + kk * 8 + tig;
                af[ti][0] = f2tf(Ab[r0]);
                af[ti][1] = f2tf(Ab[r0 + 160]);
                af[ti][2] = f2tf(Ab[r0 + 4]);
                af[ti][3] = f2tf(Ab[r0 + 164]);
            }
            #pragma unroll
            for (int tj = 0; tj < 4; tj++) {
                int r0 = (wc + tj * 8 + g) * 20 + kk * 8 + tig;
                bf[tj][0] = f2tf(Bb[r0]);
                bf[tj][1] = f2tf(Bb[r0 + 4]);
            }
            #pragma unroll
            for (int ti = 0; ti < 4; ti++)
                #pragma unroll
                for (int tj = 0; tj < 4; tj++)
                    mma_tf32(acc[ti][tj], af[ti], bf[tj]);
        }
        asm volatile("cp.async.wait_group 2;\n" ::: "memory");
        __syncthreads();
    }

    #pragma unroll
    for (int ti = 0; ti < 4; ti++) {
        #pragma unroll
        for (int rh = 0; rh < 2; rh++) {
            int gm = m0 + wr + ti * 16 + g + rh * 8;
            int bb = gm >> 11;
            int tt = gm & (T_ - 1);
            #pragma unroll
            for (int tj = 0; tj < 4; tj++) {
                int gn = n0 + wc + tj * 8 + tig * 2;
                float v0 = acc[ti][tj][rh * 2 + 0];
                float v1 = acc[ti][tj][rh * 2 + 1];
                if (MODE == 0) {
                    if (gn < N)
                        *(float2*)(Cout + (size_t)gm * ldc + gn) = make_float2(v0, v1);
                } else if (MODE == 5) {
                    if (gn < 512) {
                        *(float2*)(g_cq + (size_t)gm * 512 + gn) = make_float2(v0, v1);
                    } else if (gn < 1024) {
                        *(float2*)(g_ckv + (size_t)gm * 512 + gn - 512) = make_float2(v0, v1);
                    } else if (gn < 1088) {
                        int j = gn - 1024;
                        int p = j >> 1;
                        float c = fc[tt * 32 + p], s = fs[tt * 32 + p];
                        float o0 = v0 * c - v1 * s;
                        float o1 = v0 * s + v1 * c;
                        #pragma unroll
                        for (int hh = 0; hh < H_; hh++)
                            *(float2*)(g_k + ((size_t)(bb * H_ + hh) * T_ + tt) * D_ + HS_ + j) =
                                make_float2(o0, o1);
                    }
                } else if (MODE == 6) {
                    if (gn < 2048) {
                        int hh = gn >> 7, dd = gn & 127;
                        *(float2*)(g_q + ((size_t)(bb * H_ + hh) * T_ + tt) * D_ + dd) =
                            make_float2(v0, v1);
                    } else {
                        int j2 = gn - 2048;
                        int hh = j2 >> 6, jj = j2 & 63;
                        int p = jj >> 1;
                        float c = fc[tt * 32 + p], s = fs[tt * 32 + p];
                        *(float2*)(g_q + ((size_t)(bb * H_ + hh) * T_ + tt) * D_ + HS_ + jj) =
                            make_float2(v0 * c - v1 * s, v0 * s + v1 * c);
                    }
                } else if (MODE == 7) {
                    if (gn < 2048) {
                        int hh = gn >> 7, dd = gn & 127;
                        *(float2*)(g_k + ((size_t)(bb * H_ + hh) * T_ + tt) * D_ + dd) =
                            make_float2(v0, v1);
                    } else {
                        int t2 = gn - 2048;
                        int hh = t2 >> 7, dd = t2 & 127;
                        *(float2*)(g_v + ((size_t)(bb * H_ + hh) * T_ + tt) * HS_ + dd) =
                            make_float2(v0, v1);
                    }
                }
            }
        }
    }
}

// ---------------------------------------------------------------------------
// Fused flash attention (unchanged, proven)
// ---------------------------------------------------------------------------
#define QP  196
#define KP2 196
#define VP  68
#define PP  68
#define FLASH_SMEM_WORDS (128*QP + 64*KP2 + 128*VP + 128*PP)
#define FLASH_SMEM_BYTES (FLASH_SMEM_WORDS * 4)

__global__ void __launch_bounds__(256, 1)
flash_attn(const float* __restrict__ qg, const float* __restrict__ kg,
           const float* __restrict__ vg, float* __restrict__ ao)
{
    extern __shared__ unsigned smx[];
    unsigned* Qs = smx;
    unsigned* Ks = Qs + 128*QP;
    unsigned* Vs = Ks + 64*KP2;
    unsigned* Ps = Vs + 128*VP;

    const int z  = blockIdx.x;
    const int iy = (int)gridDim.y - 1 - blockIdx.y;
    const int q0 = iy * 128;
    const int b = z / H_, h = z % H_;

    const float* Qg = qg + (size_t)z * T_ * D_;
    const float* Kg = kg + (size_t)z * T_ * D_;
    const float* Vg = vg + (size_t)z * T_ * HS_;

    const int tid = threadIdx.x;
    const int wid = tid >> 5, lane = tid & 31;
    const int g = lane >> 2, tig = lane & 3;
    const int qrow0 = q0 + wid * 16 + g;

    #pragma unroll
    for (int it = 0; it < 24; it++) {
        int idx = tid + it * 256;
        int row = idx / 48, kq = (idx % 48) * 4;
        float4 v4 = *(const float4*)(Qg + (size_t)(q0 + row) * D_ + kq);
        unsigned* p = &Qs[row * QP + kq];
        p[0] = f2tf(v4.x); p[1] = f2tf(v4.y); p[2] = f2tf(v4.z); p[3] = f2tf(v4.w);
    }

    float m_i[2] = {-1e30f, -1e30f};
    float l_i[2] = {0.f, 0.f};
    float o[16][4];
    #pragma unroll
    for (int j = 0; j < 16; j++)
        #pragma unroll
        for (int r = 0; r < 4; r++) o[j][r] = 0.f;

    const int nkt = 2 * iy + 2;
    const float scale = 0.07216878364870323f;

    for (int kt = 0; kt < nkt; kt++) {
        __syncthreads();
        #pragma unroll
        for (int it = 0; it < 12; it++) {
            int idx = tid + it * 256;
            int row = idx / 48, kq = (idx % 48) * 4;
            float4 v4 = *(const float4*)(Kg + (size_t)(kt * 64 + row) * D_ + kq);
            unsigned* p = &Ks[row * KP2 + kq];
            p[0] = f2tf(v4.x); p[1] = f2tf(v4.y); p[2] = f2tf(v4.z); p[3] = f2tf(v4.w);
        }
        #pragma unroll
        for (int it = 0; it < 8; it++) {
            int idx = tid + it * 256;
            int kp = idx / 32, dq = (idx % 32) * 4;
            float4 v4 = *(const float4*)(Vg + (size_t)(kt * 64 + kp) * HS_ + dq);
            Vs[(dq + 0) * VP + kp] = f2tf(v4.x);
            Vs[(dq + 1) * VP + kp] = f2tf(v4.y);
            Vs[(dq + 2) * VP + kp] = f2tf(v4.z);
            Vs[(dq + 3) * VP + kp] = f2tf(v4.w);
        }
        __syncthreads();

        float s[8][4];
        #pragma unroll
        for (int j = 0; j < 8; j++)
            #pragma unroll
            for (int r = 0; r < 4; r++) s[j][r] = 0.f;

        #pragma unroll
        for (int kk = 0; kk < 24; kk++) {
            unsigned a[4];
            int r0 = (wid * 16 + g) * QP + kk * 8 + tig;
            a[0] = Qs[r0];          a[1] = Qs[r0 + 8 * QP];
            a[2] = Qs[r0 + 4];      a[3] = Qs[r0 + 8 * QP + 4];
            #pragma unroll
            for (int j = 0; j < 8; j++) {
                unsigned bq[2];
                int rb = (j * 8 + g) * KP2 + kk * 8 + tig;
                bq[0] = Ks[rb]; bq[1] = Ks[rb + 4];
                mma_tf32(s[j], a, bq);
            }
        }

        const bool diag = (kt >= 2 * iy);
        #pragma unroll
        for (int r2 = 0; r2 < 2; r2++) {
            const int row = qrow0 + r2 * 8;
            float mx = -1e30f;
            #pragma unroll
            for (int j = 0; j < 8; j++) {
                #pragma unroll
                for (int c = 0; c < 2; c++) {
                    int r = r2 * 2 + c;
                    float v = s[j][r] * scale;
                    if (diag) {
                        int col = kt * 64 + j * 8 + 2 * tig + c;
                        if (col > row) v = -1e30f;
                    }
                    s[j][r] = v;
                    mx = fmaxf(mx, v);
                }
            }
            mx = fmaxf(mx, __shfl_xor_sync(0xffffffffu, mx, 1));
            mx = fmaxf(mx, __shfl_xor_sync(0xffffffffu, mx, 2));
            float mnew = fmaxf(m_i[r2], mx);
            float alpha = __expf(m_i[r2] - mnew);
            m_i[r2] = mnew;

            float ls = 0.f;
            #pragma unroll
            for (int j = 0; j < 8; j++) {
                #pragma unroll
                for (int c = 0; c < 2; c++) {
                    int r = r2 * 2 + c;
                    float p = __expf(s[j][r] - mnew);
                    s[j][r] = p;
                    ls += p;
                }
            }
            ls += __shfl_xor_sync(0xffffffffu, ls, 1);
            ls += __shfl_xor_sync(0xffffffffu, ls, 2);
            l_i[r2] = l_i[r2] * alpha + ls;

            #pragma unroll
            for (int j = 0; j < 16; j++) {
                o[j][r2 * 2 + 0] *= alpha;
                o[j][r2 * 2 + 1] *= alpha;
            }
        }

        {
            int base0 = (wid * 16 + g) * PP;
            int base1 = (wid * 16 + g + 8) * PP;
            #pragma unroll
            for (int j = 0; j < 8; j++) {
                int cc = j * 8 + 2 * tig;
                Ps[base0 + cc    ] = f2tf(s[j][0]);
                Ps[base0 + cc + 1] = f2tf(s[j][1]);
                Ps[base1 + cc    ] = f2tf(s[j][2]);
                Ps[base1 + cc + 1] = f2tf(s[j][3]);
            }
        }
        __syncwarp();

        #pragma unroll
        for (int kk = 0; kk < 8; kk++) {
            unsigned a[4];
            int r0 = (wid * 16 + g) * PP + kk * 8 + tig;
            a[0] = Ps[r0];          a[1] = Ps[r0 + 8 * PP];
            a[2] = Ps[r0 + 4];      a[3] = Ps[r0 + 8 * PP + 4];
            #pragma unroll
            for (int j = 0; j < 16; j++) {
                unsigned bq[2];
                int rb = (j * 8 + g) * VP + kk * 8 + tig;
                bq[0] = Vs[rb]; bq[1] = Vs[rb + 4];
                mma_tf32(o[j], a, bq);
            }
        }
    }

    const float inv0 = 1.f / l_i[0];
    const float inv1 = 1.f / l_i[1];
    #pragma unroll
    for (int j = 0; j < 16; j++) {
        int d = j * 8 + 2 * tig;
        size_t base0 = ((size_t)(b * T_ + qrow0    )) * C_ + h * HS_ + d;
        size_t base1 = ((size_t)(b * T_ + qrow0 + 8)) * C_ + h * HS_ + d;
        *(float2*)(ao + base0) = make_float2(o[j][0] * inv0, o[j][1] * inv0);
        *(float2*)(ao + base1) = make_float2(o[j][2] * inv1, o[j][3] * inv1);
    }
}

// ---------------------------------------------------------------------------
// Launch
// ---------------------------------------------------------------------------
extern "C" void kernel_launch(void* const* d_in, const int* in_sizes, int n_in,
                              void* d_out, int out_size)
{
    const float* x    = (const float*)d_in[0];
    const float* fc   = (const float*)d_in[1];
    const float* fs   = (const float*)d_in[2];
    const float* Wdq  = (const float*)d_in[3];
    const float* Wuq  = (const float*)d_in[4];
    const float* Wdkv = (const float*)d_in[5];
    const float* Wuk  = (const float*)d_in[6];
    const float* Wuv  = (const float*)d_in[7];
    const float* Wqr  = (const float*)d_in[8];
    const float* Wkr  = (const float*)d_in[9];
    const float* Wo   = (const float*)d_in[10];
    float* out = (float*)d_out;

    float *cq, *ckv, *q, *k, *v, *ao;
    cudaGetSymbolAddress((void**)&cq,  g_cq);
    cudaGetSymbolAddress((void**)&ckv, g_ckv);
    cudaGetSymbolAddress((void**)&q,   g_q);
    cudaGetSymbolAddress((void**)&k,   g_k);
    cudaGetSymbolAddress((void**)&v,   g_v);
    cudaGetSymbolAddress((void**)&ao,  g_ao);

    static bool attr_set = false;
    if (!attr_set) {
        cudaFuncSetAttribute(flash_attn, cudaFuncAttributeMaxDynamicSharedMemorySize,
                             FLASH_SMEM_BYTES);
        cudaFuncSetAttribute(gemm8<0>, cudaFuncAttributeMaxDynamicSharedMemorySize,
                             GEMM_SMEM_BYTES);
        cudaFuncSetAttribute(gemm8<5>, cudaFuncAttributeMaxDynamicSharedMemorySize,
                             GEMM_SMEM_BYTES);
        cudaFuncSetAttribute(gemm8<6>, cudaFuncAttributeMaxDynamicSharedMemorySize,
                             GEMM_SMEM_BYTES);
        cudaFuncSetAttribute(gemm8<7>, cudaFuncAttributeMaxDynamicSharedMemorySize,
                             GEMM_SMEM_BYTES);
        attr_set = true;
    }

    dim3 blk(256);

    // GEMM A: x -> [c_q | c_kv | rope-bcast k_r], N=1088, K=2048
    gemm8<5><<<dim3(9, 32), blk, GEMM_SMEM_BYTES>>>(
        x, Wdq, Wdkv, Wkr, 512, 1024, 1088, C_, C_, C_, nullptr, 0, fc, fs);

    // GEMM B: c_q -> [q_c | rope q_r], N=3072, K=512
    gemm8<6><<<dim3(24, 32), blk, GEMM_SMEM_BYTES>>>(
        cq, Wuq, Wqr, Wqr, 2048, 3072, 3072, NLQ_, NLQ_, NLQ_, nullptr, 0, fc, fs);

    // GEMM C: c_kv -> [k_c | v], N=4096, K=512
    gemm8<7><<<dim3(32, 32), blk, GEMM_SMEM_BYTES>>>(
        ckv, Wuk, Wuv, Wuv, 2048, 4096, 4096, NLKV_, NLKV_, NLKV_, nullptr, 0, fc, fs);

    // Fused flash attention
    dim3 gfa(B_ * H_, T_ / 128);
    flash_attn<<<gfa, 256, FLASH_SMEM_BYTES>>>(q, k, v, ao);

    // Output projection
    gemm8<0><<<dim3(16, 32), blk, GEMM_SMEM_BYTES>>>(
        ao, Wo, Wo, Wo, 4096, 8192, 2048, C_, C_, C_, out, C_, fc, fs);
}

// round 7
// speedup vs baseline: 4.5374x; 1.0682x over previous
#include <cuda_runtime.h>
#include <math.h>

#define B_   2
#define T_   2048
#define C_   2048
#define H_   16
#define HS_  128
#define NLQ_ 512
#define NLKV_ 512
#define RHD_ 64
#define D_   192

__device__ float g_cq [B_*T_*NLQ_];
__device__ float g_ckv[B_*T_*NLKV_];
__device__ float g_q  [B_*H_*T_*D_];
__device__ float g_k  [B_*H_*T_*D_];
__device__ float g_v  [B_*H_*T_*HS_];
__device__ float g_ao [B_*T_*C_];

__device__ __forceinline__ unsigned f2tf(float f) {
    unsigned u;
    asm("cvt.rna.tf32.f32 %0, %1;" : "=r"(u) : "f"(f));
    return u;
}
__device__ __forceinline__ void mma_tf32(float* d, const unsigned* a, const unsigned* b) {
    asm volatile(
        "mma.sync.aligned.m16n8k8.row.col.f32.tf32.tf32.f32 "
        "{%0,%1,%2,%3}, {%4,%5,%6,%7}, {%8,%9}, {%0,%1,%2,%3};"
        : "+f"(d[0]), "+f"(d[1]), "+f"(d[2]), "+f"(d[3])
        : "r"(a[0]), "r"(a[1]), "r"(a[2]), "r"(a[3]), "r"(b[0]), "r"(b[1]));
}
__device__ __forceinline__ void cp16(float* dst, const float* src, bool valid) {
    unsigned d = (unsigned)__cvta_generic_to_shared(dst);
    int sz = valid ? 16 : 0;
    asm volatile("cp.async.cg.shared.global [%0], [%1], 16, %2;\n"
                 :: "r"(d), "l"(src), "r"(sz) : "memory");
}

// ---------------------------------------------------------------------------
// 4-stage cp.async tf32 GEMM, NT. 256 threads, 8 warps as 4m x 2n,
// warp tile m32 x n64 (1.5 smem words per MMA). M fixed = 4096.
// B side = up to 3 row-concatenated weight matrices (split nb1/nb2).
// MODE 0: plain Cout ; 5: x-proj split ; 6: cq-proj ; 7: ckv-proj
// ---------------------------------------------------------------------------
#define GEMM_SMEM_BYTES (8 * 2560 * 4)   // 81920

template<int MODE>
__global__ void __launch_bounds__(256, 2)
gemm8(const float* __restrict__ A,
      const float* __restrict__ B0, const float* __restrict__ B1,
      const float* __restrict__ B2, int nb1, int nb2,
      int N, int K, int lda, int ldb,
      float* __restrict__ Cout, int ldc,
      const float* __restrict__ fc, const float* __restrict__ fs)
{
    extern __shared__ float gsm[];
    float* As = gsm;             // 4 stages x 128 x 20
    float* Bs = gsm + 4 * 2560;

    const int m0 = blockIdx.y * 128;
    const int n0 = blockIdx.x * 128;
    const int tid  = threadIdx.x;
    const int wid  = tid >> 5;
    const int lane = tid & 31;
    const int g    = lane >> 2;
    const int tig  = lane & 3;
    const int wr   = (wid & 3) * 32;    // 4 m-warps
    const int wc   = (wid >> 2) * 64;   // 2 n-warps
    const int lrow = tid >> 2;          // 0..63
    const int lkq  = (tid & 3) * 4;
    const int nk   = K / 16;

    float acc[2][8][4];
    #pragma unroll
    for (int i = 0; i < 2; i++)
        #pragma unroll
        for (int j = 0; j < 8; j++)
            #pragma unroll
            for (int r = 0; r < 4; r++) acc[i][j][r] = 0.f;

    auto issue = [&](int kt) {
        int s = kt & 3;
        #pragma unroll
        for (int i = 0; i < 2; i++) {
            int r = lrow + i * 64;
            cp16(As + s * 2560 + r * 20 + lkq,
                 A + (size_t)(m0 + r) * lda + kt * 16 + lkq, true);
            int br = n0 + r;
            const float* bp = (br < nb1) ? B0 + (size_t)br * ldb
                            : (br < nb2) ? B1 + (size_t)(br - nb1) * ldb
                                         : B2 + (size_t)(br - nb2) * ldb;
            cp16(Bs + s * 2560 + r * 20 + lkq, bp + kt * 16 + lkq, br < N);
        }
        asm volatile("cp.async.commit_group;\n" ::: "memory");
    };

    issue(0); issue(1); issue(2);
    asm volatile("cp.async.wait_group 2;\n" ::: "memory");
    __syncthreads();

    for (int kt = 0; kt < nk; kt++) {
        if (kt + 3 < nk) issue(kt + 3);
        else asm volatile("cp.async.commit_group;\n" ::: "memory");

        const float* Ab = As + (kt & 3) * 2560;
        const float* Bb = Bs + (kt & 3) * 2560;
        #pragma unroll
        for (int kk = 0; kk < 2; kk++) {
            unsigned af[2][4], bf[8][2];
            #pragma unroll
            for (int ti = 0; ti < 2; ti++) {
                int r0 = (wr + ti * 16 + g) * 20 + kk * 8 + tig;
                af[ti][0] = f2tf(Ab[r0]);
                af[ti][1] = f2tf(Ab[r0 + 160]);
                af[ti][2] = f2tf(Ab[r0 + 4]);
                af[ti][3] = f2tf(Ab[r0 + 164]);
            }
            #pragma unroll
            for (int tj = 0; tj < 8; tj++) {
                int r0 = (wc + tj * 8 + g) * 20 + kk * 8 + tig;
                bf[tj][0] = f2tf(Bb[r0]);
                bf[tj][1] = f2tf(Bb[r0 + 4]);
            }
            #pragma unroll
            for (int ti = 0; ti < 2; ti++)
                #pragma unroll
                for (int tj = 0; tj < 8; tj++)
                    mma_tf32(acc[ti][tj], af[ti], bf[tj]);
        }
        asm volatile("cp.async.wait_group 2;\n" ::: "memory");
        __syncthreads();
    }

    #pragma unroll
    for (int ti = 0; ti < 2; ti++) {
        #pragma unroll
        for (int rh = 0; rh < 2; rh++) {
            int gm = m0 + wr + ti * 16 + g + rh * 8;
            int bb = gm >> 11;
            int tt = gm & (T_ - 1);
            #pragma unroll
            for (int tj = 0; tj < 8; tj++) {
                int gn = n0 + wc + tj * 8 + tig * 2;
                float v0 = acc[ti][tj][rh * 2 + 0];
                float v1 = acc[ti][tj][rh * 2 + 1];
                if (MODE == 0) {
                    if (gn < N)
                        *(float2*)(Cout + (size_t)gm * ldc + gn) = make_float2(v0, v1);
                } else if (MODE == 5) {
                    if (gn < 512) {
                        *(float2*)(g_cq + (size_t)gm * 512 + gn) = make_float2(v0, v1);
                    } else if (gn < 1024) {
                        *(float2*)(g_ckv + (size_t)gm * 512 + gn - 512) = make_float2(v0, v1);
                    } else if (gn < 1088) {
                        int j = gn - 1024;
                        int p = j >> 1;
                        float c = fc[tt * 32 + p], s = fs[tt * 32 + p];
                        float o0 = v0 * c - v1 * s;
                        float o1 = v0 * s + v1 * c;
                        #pragma unroll
                        for (int hh = 0; hh < H_; hh++)
                            *(float2*)(g_k + ((size_t)(bb * H_ + hh) * T_ + tt) * D_ + HS_ + j) =
                                make_float2(o0, o1);
                    }
                } else if (MODE == 6) {
                    if (gn < 2048) {
                        int hh = gn >> 7, dd = gn & 127;
                        *(float2*)(g_q + ((size_t)(bb * H_ + hh) * T_ + tt) * D_ + dd) =
                            make_float2(v0, v1);
                    } else {
                        int j2 = gn - 2048;
                        int hh = j2 >> 6, jj = j2 & 63;
                        int p = jj >> 1;
                        float c = fc[tt * 32 + p], s = fs[tt * 32 + p];
                        *(float2*)(g_q + ((size_t)(bb * H_ + hh) * T_ + tt) * D_ + HS_ + jj) =
                            make_float2(v0 * c - v1 * s, v0 * s + v1 * c);
                    }
                } else if (MODE == 7) {
                    if (gn < 2048) {
                        int hh = gn >> 7, dd = gn & 127;
                        *(float2*)(g_k + ((size_t)(bb * H_ + hh) * T_ + tt) * D_ + dd) =
                            make_float2(v0, v1);
                    } else {
                        int t2 = gn - 2048;
                        int hh = t2 >> 7, dd = t2 & 127;
                        *(float2*)(g_v + ((size_t)(bb * H_ + hh) * T_ + tt) * HS_ + dd) =
                            make_float2(v0, v1);
                    }
                }
            }
        }
    }
}

// ---------------------------------------------------------------------------
// Fused flash attention v3: cp.async fills with split waits.
// Q raw [128][196], K raw [64][196], V raw key-major [64][132], P tf32 [128][68].
// Per tile: wait K -> S+softmax (V fill in flight) -> wait V -> prefetch K(t+1)
// -> PV -> prefetch V(t+1).
// ---------------------------------------------------------------------------
#define QP   196
#define KSP  196
#define VSP  132
#define PP   68
#define FLASH_SMEM_WORDS (128*QP + 64*KSP + 64*VSP + 128*PP)   // 54784
#define FLASH_SMEM_BYTES (FLASH_SMEM_WORDS * 4)                // 219136

__global__ void __launch_bounds__(256, 1)
flash_attn(const float* __restrict__ qg, const float* __restrict__ kg,
           const float* __restrict__ vg, float* __restrict__ ao)
{
    extern __shared__ float smf[];
    float* Qs = smf;                       // [row][k]
    float* Ks = Qs + 128 * QP;             // [key][k]
    float* Vs = Ks + 64 * KSP;             // [key][d]
    unsigned* Ps = (unsigned*)(Vs + 64 * VSP);  // [row][key] tf32

    const int z  = blockIdx.x;
    const int iy = (int)gridDim.y - 1 - blockIdx.y;
    const int q0 = iy * 128;
    const int b = z / H_, h = z % H_;

    const float* Qg = qg + (size_t)z * T_ * D_;
    const float* Kg = kg + (size_t)z * T_ * D_;
    const float* Vg = vg + (size_t)z * T_ * HS_;

    const int tid = threadIdx.x;
    const int wid = tid >> 5, lane = tid & 31;
    const int g = lane >> 2, tig = lane & 3;
    const int qrow0 = q0 + wid * 16 + g;

    auto issueK = [&](int kt) {
        #pragma unroll
        for (int it = 0; it < 12; it++) {
            int idx = tid + it * 256;
            int row = idx / 48, kq = (idx % 48) * 4;
            cp16(Ks + row * KSP + kq, Kg + (size_t)(kt * 64 + row) * D_ + kq, true);
        }
        asm volatile("cp.async.commit_group;\n" ::: "memory");
    };
    auto issueV = [&](int kt) {
        #pragma unroll
        for (int it = 0; it < 8; it++) {
            int idx = tid + it * 256;
            int kp = idx / 32, dq = (idx % 32) * 4;
            cp16(Vs + kp * VSP + dq, Vg + (size_t)(kt * 64 + kp) * HS_ + dq, true);
        }
        asm volatile("cp.async.commit_group;\n" ::: "memory");
    };

    // Prologue: Q + K0 in group 1, V0 in group 2
    #pragma unroll
    for (int it = 0; it < 24; it++) {
        int idx = tid + it * 256;
        int row = idx / 48, kq = (idx % 48) * 4;
        cp16(Qs + row * QP + kq, Qg + (size_t)(q0 + row) * D_ + kq, true);
    }
    issueK(0);   // commits Q + K0 together
    issueV(0);

    float m_i[2] = {-1e30f, -1e30f};
    float l_i[2] = {0.f, 0.f};
    float o[16][4];
    #pragma unroll
    for (int j = 0; j < 16; j++)
        #pragma unroll
        for (int r = 0; r < 4; r++) o[j][r] = 0.f;

    const int nkt = 2 * iy + 2;
    const float scale = 0.07216878364870323f;

    for (int kt = 0; kt < nkt; kt++) {
        asm volatile("cp.async.wait_group 1;\n" ::: "memory");  // Q+K ready
        __syncthreads();

        // S = Q K^T : warp m16 x n64, k=192 (raw floats, cvt on load)
        float s[8][4];
        #pragma unroll
        for (int j = 0; j < 8; j++)
            #pragma unroll
            for (int r = 0; r < 4; r++) s[j][r] = 0.f;

        #pragma unroll
        for (int kk = 0; kk < 24; kk++) {
            unsigned a[4];
            int r0 = (wid * 16 + g) * QP + kk * 8 + tig;
            a[0] = f2tf(Qs[r0]);          a[1] = f2tf(Qs[r0 + 8 * QP]);
            a[2] = f2tf(Qs[r0 + 4]);      a[3] = f2tf(Qs[r0 + 8 * QP + 4]);
            #pragma unroll
            for (int j = 0; j < 8; j++) {
                unsigned bq[2];
                int rb = (j * 8 + g) * KSP + kk * 8 + tig;
                bq[0] = f2tf(Ks[rb]); bq[1] = f2tf(Ks[rb + 4]);
                mma_tf32(s[j], a, bq);
            }
        }

        // Online softmax
        const bool diag = (kt >= 2 * iy);
        #pragma unroll
        for (int r2 = 0; r2 < 2; r2++) {
            const int row = qrow0 + r2 * 8;
            float mx = -1e30f;
            #pragma unroll
            for (int j = 0; j < 8; j++) {
                #pragma unroll
                for (int c = 0; c < 2; c++) {
                    int r = r2 * 2 + c;
                    float v = s[j][r] * scale;
                    if (diag) {
                        int col = kt * 64 + j * 8 + 2 * tig + c;
                        if (col > row) v = -1e30f;
                    }
                    s[j][r] = v;
                    mx = fmaxf(mx, v);
                }
            }
            mx = fmaxf(mx, __shfl_xor_sync(0xffffffffu, mx, 1));
            mx = fmaxf(mx, __shfl_xor_sync(0xffffffffu, mx, 2));
            float mnew = fmaxf(m_i[r2], mx);
            float alpha = __expf(m_i[r2] - mnew);
            m_i[r2] = mnew;

            float ls = 0.f;
            #pragma unroll
            for (int j = 0; j < 8; j++) {
                #pragma unroll
                for (int c = 0; c < 2; c++) {
                    int r = r2 * 2 + c;
                    float p = __expf(s[j][r] - mnew);
                    s[j][r] = p;
                    ls += p;
                }
            }
            ls += __shfl_xor_sync(0xffffffffu, ls, 1);
            ls += __shfl_xor_sync(0xffffffffu, ls, 2);
            l_i[r2] = l_i[r2] * alpha + ls;

            #pragma unroll
            for (int j = 0; j < 16; j++) {
                o[j][r2 * 2 + 0] *= alpha;
                o[j][r2 * 2 + 1] *= alpha;
            }
        }

        // P -> smem (tf32, per-warp rows)
        {
            int base0 = (wid * 16 + g) * PP;
            int base1 = (wid * 16 + g + 8) * PP;
            #pragma unroll
            for (int j = 0; j < 8; j++) {
                int cc = j * 8 + 2 * tig;
                Ps[base0 + cc    ] = f2tf(s[j][0]);
                Ps[base0 + cc + 1] = f2tf(s[j][1]);
                Ps[base1 + cc    ] = f2tf(s[j][2]);
                Ps[base1 + cc + 1] = f2tf(s[j][3]);
            }
        }
        __syncwarp();

        asm volatile("cp.async.wait_group 0;\n" ::: "memory");  // V ready
        __syncthreads();                                        // + all done with K

        if (kt + 1 < nkt) issueK(kt + 1);   // prefetch next K during PV
        else asm volatile("cp.async.commit_group;\n" ::: "memory");

        // O += P V : warp m16 x n128, k=64 ; V key-major raw
        #pragma unroll
        for (int kk = 0; kk < 8; kk++) {
            unsigned a[4];
            int r0 = (wid * 16 + g) * PP + kk * 8 + tig;
            a[0] = Ps[r0];          a[1] = Ps[r0 + 8 * PP];
            a[2] = Ps[r0 + 4];      a[3] = Ps[r0 + 8 * PP + 4];
            #pragma unroll
            for (int j = 0; j < 16; j++) {
                unsigned bq[2];
                int cb = j * 8 + g;
                bq[0] = f2tf(Vs[(kk * 8 + tig    ) * VSP + cb]);
                bq[1] = f2tf(Vs[(kk * 8 + tig + 4) * VSP + cb]);
                mma_tf32(o[j], a, bq);
            }
        }

        __syncthreads();                    // all done reading V
        if (kt + 1 < nkt) issueV(kt + 1);
        else asm volatile("cp.async.commit_group;\n" ::: "memory");
    }

    const float inv0 = 1.f / l_i[0];
    const float inv1 = 1.f / l_i[1];
    #pragma unroll
    for (int j = 0; j < 16; j++) {
        int d = j * 8 + 2 * tig;
        size_t base0 = ((size_t)(b * T_ + qrow0    )) * C_ + h * HS_ + d;
        size_t base1 = ((size_t)(b * T_ + qrow0 + 8)) * C_ + h * HS_ + d;
        *(float2*)(ao + base0) = make_float2(o[j][0] * inv0, o[j][1] * inv0);
        *(float2*)(ao + base1) = make_float2(o[j][2] * inv1, o[j][3] * inv1);
    }
}

// ---------------------------------------------------------------------------
// Launch
// ---------------------------------------------------------------------------
extern "C" void kernel_launch(void* const* d_in, const int* in_sizes, int n_in,
                              void* d_out, int out_size)
{
    const float* x    = (const float*)d_in[0];
    const float* fc   = (const float*)d_in[1];
    const float* fs   = (const float*)d_in[2];
    const float* Wdq  = (const float*)d_in[3];
    const float* Wuq  = (const float*)d_in[4];
    const float* Wdkv = (const float*)d_in[5];
    const float* Wuk  = (const float*)d_in[6];
    const float* Wuv  = (const float*)d_in[7];
    const float* Wqr  = (const float*)d_in[8];
    const float* Wkr  = (const float*)d_in[9];
    const float* Wo   = (const float*)d_in[10];
    float* out = (float*)d_out;

    float *cq, *ckv, *q, *k, *v, *ao;
    cudaGetSymbolAddress((void**)&cq,  g_cq);
    cudaGetSymbolAddress((void**)&ckv, g_ckv);
    cudaGetSymbolAddress((void**)&q,   g_q);
    cudaGetSymbolAddress((void**)&k,   g_k);
    cudaGetSymbolAddress((void**)&v,   g_v);
    cudaGetSymbolAddress((void**)&ao,  g_ao);

    static bool attr_set = false;
    if (!attr_set) {
        cudaFuncSetAttribute(flash_attn, cudaFuncAttributeMaxDynamicSharedMemorySize,
                             FLASH_SMEM_BYTES);
        cudaFuncSetAttribute(gemm8<0>, cudaFuncAttributeMaxDynamicSharedMemorySize,
                             GEMM_SMEM_BYTES);
        cudaFuncSetAttribute(gemm8<5>, cudaFuncAttributeMaxDynamicSharedMemorySize,
                             GEMM_SMEM_BYTES);
        cudaFuncSetAttribute(gemm8<6>, cudaFuncAttributeMaxDynamicSharedMemorySize,
                             GEMM_SMEM_BYTES);
        cudaFuncSetAttribute(gemm8<7>, cudaFuncAttributeMaxDynamicSharedMemorySize,
                             GEMM_SMEM_BYTES);
        attr_set = true;
    }

    dim3 blk(256);

    // GEMM A: x -> [c_q | c_kv | rope-bcast k_r], N=1088, K=2048
    gemm8<5><<<dim3(9, 32), blk, GEMM_SMEM_BYTES>>>(
        x, Wdq, Wdkv, Wkr, 512, 1024, 1088, C_, C_, C_, nullptr, 0, fc, fs);

    // GEMM B: c_q -> [q_c | rope q_r], N=3072, K=512
    gemm8<6><<<dim3(24, 32), blk, GEMM_SMEM_BYTES>>>(
        cq, Wuq, Wqr, Wqr, 2048, 3072, 3072, NLQ_, NLQ_, NLQ_, nullptr, 0, fc, fs);

    // GEMM C: c_kv -> [k_c | v], N=4096, K=512
    gemm8<7><<<dim3(32, 32), blk, GEMM_SMEM_BYTES>>>(
        ckv, Wuk, Wuv, Wuv, 2048, 4096, 4096, NLKV_, NLKV_, NLKV_, nullptr, 0, fc, fs);

    // Fused flash attention
    dim3 gfa(B_ * H_, T_ / 128);
    flash_attn<<<gfa, 256, FLASH_SMEM_BYTES>>>(q, k, v, ao);

    // Output projection
    gemm8<0><<<dim3(16, 32), blk, GEMM_SMEM_BYTES>>>(
        ao, Wo, Wo, Wo, 4096, 8192, 2048, C_, C_, C_, out, C_, fc, fs);
}

// round 8
// speedup vs baseline: 4.7059x; 1.0371x over previous
#include <cuda_runtime.h>
#include <math.h>

#define B_   2
#define T_   2048
#define C_   2048
#define H_   16
#define HS_  128
#define NLQ_ 512
#define NLKV_ 512
#define RHD_ 64
#define D_   192

__device__ float g_cq [B_*T_*NLQ_];
__device__ float g_ckv[B_*T_*NLKV_];
__device__ float g_q  [B_*H_*T_*D_];    // stored pre-rounded to tf32
__device__ float g_k  [B_*H_*T_*D_];    // stored pre-rounded to tf32
__device__ float g_v  [B_*H_*T_*HS_];   // stored pre-rounded to tf32
__device__ float g_ao [B_*T_*C_];

__device__ __forceinline__ unsigned f2tf(float f) {
    unsigned u;
    asm("cvt.rna.tf32.f32 %0, %1;" : "=r"(u) : "f"(f));
    return u;
}
__device__ __forceinline__ float2 tf2(float a, float b) {
    return make_float2(__uint_as_float(f2tf(a)), __uint_as_float(f2tf(b)));
}
__device__ __forceinline__ void mma_tf32(float* d, const unsigned* a, const unsigned* b) {
    asm volatile(
        "mma.sync.aligned.m16n8k8.row.col.f32.tf32.tf32.f32 "
        "{%0,%1,%2,%3}, {%4,%5,%6,%7}, {%8,%9}, {%0,%1,%2,%3};"
        : "+f"(d[0]), "+f"(d[1]), "+f"(d[2]), "+f"(d[3])
        : "r"(a[0]), "r"(a[1]), "r"(a[2]), "r"(a[3]), "r"(b[0]), "r"(b[1]));
}
__device__ __forceinline__ void cp16(void* dst, const void* src, bool valid) {
    unsigned d = (unsigned)__cvta_generic_to_shared(dst);
    int sz = valid ? 16 : 0;
    asm volatile("cp.async.cg.shared.global [%0], [%1], 16, %2;\n"
                 :: "r"(d), "l"(src), "r"(sz) : "memory");
}

// ---------------------------------------------------------------------------
// 4-stage cp.async tf32 GEMM, NT. 256 threads, 8 warps as 4m x 2n,
// warp tile m32 x n64. M fixed = 4096.
// B side = up to 3 row-concatenated weight matrices (split nb1/nb2).
// MODE 0: plain Cout ; 5: x-proj split ; 6: cq-proj ; 7: ckv-proj
// MODEs 5/6/7 write tf32-pre-rounded values into g_q/g_k/g_v.
// ---------------------------------------------------------------------------
#define GEMM_SMEM_BYTES (8 * 2560 * 4)   // 81920

template<int MODE>
__global__ void __launch_bounds__(256, 2)
gemm8(const float* __restrict__ A,
      const float* __restrict__ B0, const float* __restrict__ B1,
      const float* __restrict__ B2, int nb1, int nb2,
      int N, int K, int lda, int ldb,
      float* __restrict__ Cout, int ldc,
      const float* __restrict__ fc, const float* __restrict__ fs)
{
    extern __shared__ float gsm[];
    float* As = gsm;             // 4 stages x 128 x 20
    float* Bs = gsm + 4 * 2560;

    const int m0 = blockIdx.y * 128;
    const int n0 = blockIdx.x * 128;
    const int tid  = threadIdx.x;
    const int wid  = tid >> 5;
    const int lane = tid & 31;
    const int g    = lane >> 2;
    const int tig  = lane & 3;
    const int wr   = (wid & 3) * 32;
    const int wc   = (wid >> 2) * 64;
    const int lrow = tid >> 2;
    const int lkq  = (tid & 3) * 4;
    const int nk   = K / 16;

    float acc[2][8][4];
    #pragma unroll
    for (int i = 0; i < 2; i++)
        #pragma unroll
        for (int j = 0; j < 8; j++)
            #pragma unroll
            for (int r = 0; r < 4; r++) acc[i][j][r] = 0.f;

    auto issue = [&](int kt) {
        int s = kt & 3;
        #pragma unroll
        for (int i = 0; i < 2; i++) {
            int r = lrow + i * 64;
            cp16(As + s * 2560 + r * 20 + lkq,
                 A + (size_t)(m0 + r) * lda + kt * 16 + lkq, true);
            int br = n0 + r;
            const float* bp = (br < nb1) ? B0 + (size_t)br * ldb
                            : (br < nb2) ? B1 + (size_t)(br - nb1) * ldb
                                         : B2 + (size_t)(br - nb2) * ldb;
            cp16(Bs + s * 2560 + r * 20 + lkq, bp + kt * 16 + lkq, br < N);
        }
        asm volatile("cp.async.commit_group;\n" ::: "memory");
    };

    issue(0); issue(1); issue(2);
    asm volatile("cp.async.wait_group 2;\n" ::: "memory");
    __syncthreads();

    for (int kt = 0; kt < nk; kt++) {
        if (kt + 3 < nk) issue(kt + 3);
        else asm volatile("cp.async.commit_group;\n" ::: "memory");

        const float* Ab = As + (kt & 3) * 2560;
        const float* Bb = Bs + (kt & 3) * 2560;
        #pragma unroll
        for (int kk = 0; kk < 2; kk++) {
            unsigned af[2][4], bf[8][2];
            #pragma unroll
            for (int ti = 0; ti < 2; ti++) {
                int r0 = (wr + ti * 16 + g) * 20 + kk * 8 + tig;
                af[ti][0] = f2tf(Ab[r0]);
                af[ti][1] = f2tf(Ab[r0 + 160]);
                af[ti][2] = f2tf(Ab[r0 + 4]);
                af[ti][3] = f2tf(Ab[r0 + 164]);
            }
            #pragma unroll
            for (int tj = 0; tj < 8; tj++) {
                int r0 = (wc + tj * 8 + g) * 20 + kk * 8 + tig;
                bf[tj][0] = f2tf(Bb[r0]);
                bf[tj][1] = f2tf(Bb[r0 + 4]);
            }
            #pragma unroll
            for (int ti = 0; ti < 2; ti++)
                #pragma unroll
                for (int tj = 0; tj < 8; tj++)
                    mma_tf32(acc[ti][tj], af[ti], bf[tj]);
        }
        asm volatile("cp.async.wait_group 2;\n" ::: "memory");
        __syncthreads();
    }

    #pragma unroll
    for (int ti = 0; ti < 2; ti++) {
        #pragma unroll
        for (int rh = 0; rh < 2; rh++) {
            int gm = m0 + wr + ti * 16 + g + rh * 8;
            int bb = gm >> 11;
            int tt = gm & (T_ - 1);
            #pragma unroll
            for (int tj = 0; tj < 8; tj++) {
                int gn = n0 + wc + tj * 8 + tig * 2;
                float v0 = acc[ti][tj][rh * 2 + 0];
                float v1 = acc[ti][tj][rh * 2 + 1];
                if (MODE == 0) {
                    if (gn < N)
                        *(float2*)(Cout + (size_t)gm * ldc + gn) = make_float2(v0, v1);
                } else if (MODE == 5) {
                    if (gn < 512) {
                        *(float2*)(g_cq + (size_t)gm * 512 + gn) = make_float2(v0, v1);
                    } else if (gn < 1024) {
                        *(float2*)(g_ckv + (size_t)gm * 512 + gn - 512) = make_float2(v0, v1);
                    } else if (gn < 1088) {
                        int j = gn - 1024;
                        int p = j >> 1;
                        float c = fc[tt * 32 + p], s = fs[tt * 32 + p];
                        float2 o2 = tf2(v0 * c - v1 * s, v0 * s + v1 * c);
                        #pragma unroll
                        for (int hh = 0; hh < H_; hh++)
                            *(float2*)(g_k + ((size_t)(bb * H_ + hh) * T_ + tt) * D_ + HS_ + j) = o2;
                    }
                } else if (MODE == 6) {
                    if (gn < 2048) {
                        int hh = gn >> 7, dd = gn & 127;
                        *(float2*)(g_q + ((size_t)(bb * H_ + hh) * T_ + tt) * D_ + dd) =
                            tf2(v0, v1);
                    } else {
                        int j2 = gn - 2048;
                        int hh = j2 >> 6, jj = j2 & 63;
                        int p = jj >> 1;
                        float c = fc[tt * 32 + p], s = fs[tt * 32 + p];
                        *(float2*)(g_q + ((size_t)(bb * H_ + hh) * T_ + tt) * D_ + HS_ + jj) =
                            tf2(v0 * c - v1 * s, v0 * s + v1 * c);
                    }
                } else if (MODE == 7) {
                    if (gn < 2048) {
                        int hh = gn >> 7, dd = gn & 127;
                        *(float2*)(g_k + ((size_t)(bb * H_ + hh) * T_ + tt) * D_ + dd) =
                            tf2(v0, v1);
                    } else {
                        int t2 = gn - 2048;
                        int hh = t2 >> 7, dd = t2 & 127;
                        *(float2*)(g_v + ((size_t)(bb * H_ + hh) * T_ + tt) * HS_ + dd) =
                            tf2(v0, v1);
                    }
                }
            }
        }
    }
}

// ---------------------------------------------------------------------------
// Fused flash attention v4: inputs pre-rounded to tf32 in gmem, so fragment
// loads are raw LDS (zero CVT in the inner loops). cp.async split-wait
// pipeline as in v3.
// ---------------------------------------------------------------------------
#define QP   196
#define KSP  196
#define VSP  132
#define PP   68
#define FLASH_SMEM_WORDS (128*QP + 64*KSP + 64*VSP + 128*PP)   // 54784
#define FLASH_SMEM_BYTES (FLASH_SMEM_WORDS * 4)                // 219136

__global__ void __launch_bounds__(256, 1)
flash_attn(const float* __restrict__ qg, const float* __restrict__ kg,
           const float* __restrict__ vg, float* __restrict__ ao)
{
    extern __shared__ unsigned smu[];
    unsigned* Qs = smu;                    // [row][k]  (tf32 bits)
    unsigned* Ks = Qs + 128 * QP;          // [key][k]
    unsigned* Vs = Ks + 64 * KSP;          // [key][d]
    unsigned* Ps = Vs + 64 * VSP;          // [row][key] tf32

    const int z  = blockIdx.x;
    const int iy = (int)gridDim.y - 1 - blockIdx.y;
    const int q0 = iy * 128;
    const int b = z / H_, h = z % H_;

    const float* Qg = qg + (size_t)z * T_ * D_;
    const float* Kg = kg + (size_t)z * T_ * D_;
    const float* Vg = vg + (size_t)z * T_ * HS_;

    const int tid = threadIdx.x;
    const int wid = tid >> 5, lane = tid & 31;
    const int g = lane >> 2, tig = lane & 3;
    const int qrow0 = q0 + wid * 16 + g;

    auto issueK = [&](int kt) {
        #pragma unroll
        for (int it = 0; it < 12; it++) {
            int idx = tid + it * 256;
            int row = idx / 48, kq = (idx % 48) * 4;
            cp16(Ks + row * KSP + kq, Kg + (size_t)(kt * 64 + row) * D_ + kq, true);
        }
        asm volatile("cp.async.commit_group;\n" ::: "memory");
    };
    auto issueV = [&](int kt) {
        #pragma unroll
        for (int it = 0; it < 8; it++) {
            int idx = tid + it * 256;
            int kp = idx / 32, dq = (idx % 32) * 4;
            cp16(Vs + kp * VSP + dq, Vg + (size_t)(kt * 64 + kp) * HS_ + dq, true);
        }
        asm volatile("cp.async.commit_group;\n" ::: "memory");
    };

    // Prologue: Q + K0 in one group, V0 in the next
    #pragma unroll
    for (int it = 0; it < 24; it++) {
        int idx = tid + it * 256;
        int row = idx / 48, kq = (idx % 48) * 4;
        cp16(Qs + row * QP + kq, Qg + (size_t)(q0 + row) * D_ + kq, true);
    }
    issueK(0);
    issueV(0);

    float m_i[2] = {-1e30f, -1e30f};
    float l_i[2] = {0.f, 0.f};
    float o[16][4];
    #pragma unroll
    for (int j = 0; j < 16; j++)
        #pragma unroll
        for (int r = 0; r < 4; r++) o[j][r] = 0.f;

    const int nkt = 2 * iy + 2;
    const float scale = 0.07216878364870323f;

    for (int kt = 0; kt < nkt; kt++) {
        asm volatile("cp.async.wait_group 1;\n" ::: "memory");  // Q+K ready
        __syncthreads();

        // S = Q K^T : warp m16 x n64, k=192 (raw tf32 bits, no cvt)
        float s[8][4];
        #pragma unroll
        for (int j = 0; j < 8; j++)
            #pragma unroll
            for (int r = 0; r < 4; r++) s[j][r] = 0.f;

        #pragma unroll
        for (int kk = 0; kk < 24; kk++) {
            unsigned a[4];
            int r0 = (wid * 16 + g) * QP + kk * 8 + tig;
            a[0] = Qs[r0];          a[1] = Qs[r0 + 8 * QP];
            a[2] = Qs[r0 + 4];      a[3] = Qs[r0 + 8 * QP + 4];
            #pragma unroll
            for (int j = 0; j < 8; j++) {
                unsigned bq[2];
                int rb = (j * 8 + g) * KSP + kk * 8 + tig;
                bq[0] = Ks[rb]; bq[1] = Ks[rb + 4];
                mma_tf32(s[j], a, bq);
            }
        }

        // Online softmax
        const bool diag = (kt >= 2 * iy);
        #pragma unroll
        for (int r2 = 0; r2 < 2; r2++) {
            const int row = qrow0 + r2 * 8;
            float mx = -1e30f;
            #pragma unroll
            for (int j = 0; j < 8; j++) {
                #pragma unroll
                for (int c = 0; c < 2; c++) {
                    int r = r2 * 2 + c;
                    float v = s[j][r] * scale;
                    if (diag) {
                        int col = kt * 64 + j * 8 + 2 * tig + c;
                        if (col > row) v = -1e30f;
                    }
                    s[j][r] = v;
                    mx = fmaxf(mx, v);
                }
            }
            mx = fmaxf(mx, __shfl_xor_sync(0xffffffffu, mx, 1));
            mx = fmaxf(mx, __shfl_xor_sync(0xffffffffu, mx, 2));
            float mnew = fmaxf(m_i[r2], mx);
            float alpha = __expf(m_i[r2] - mnew);
            m_i[r2] = mnew;

            float ls = 0.f;
            #pragma unroll
            for (int j = 0; j < 8; j++) {
                #pragma unroll
                for (int c = 0; c < 2; c++) {
                    int r = r2 * 2 + c;
                    float p = __expf(s[j][r] - mnew);
                    s[j][r] = p;
                    ls += p;
                }
            }
            ls += __shfl_xor_sync(0xffffffffu, ls, 1);
            ls += __shfl_xor_sync(0xffffffffu, ls, 2);
            l_i[r2] = l_i[r2] * alpha + ls;

            #pragma unroll
            for (int j = 0; j < 16; j++) {
                o[j][r2 * 2 + 0] *= alpha;
                o[j][r2 * 2 + 1] *= alpha;
            }
        }

        // P -> smem (tf32, per-warp rows)
        {
            int base0 = (wid * 16 + g) * PP;
            int base1 = (wid * 16 + g + 8) * PP;
            #pragma unroll
            for (int j = 0; j < 8; j++) {
                int cc = j * 8 + 2 * tig;
                Ps[base0 + cc    ] = f2tf(s[j][0]);
                Ps[base0 + cc + 1] = f2tf(s[j][1]);
                Ps[base1 + cc    ] = f2tf(s[j][2]);
                Ps[base1 + cc + 1] = f2tf(s[j][3]);
            }
        }
        __syncwarp();

        asm volatile("cp.async.wait_group 0;\n" ::: "memory");  // V ready
        __syncthreads();                                        // + done with K

        if (kt + 1 < nkt) issueK(kt + 1);   // prefetch next K during PV
        else asm volatile("cp.async.commit_group;\n" ::: "memory");

        // O += P V : warp m16 x n128, k=64 ; V key-major, raw tf32 bits
        #pragma unroll
        for (int kk = 0; kk < 8; kk++) {
            unsigned a[4];
            int r0 = (wid * 16 + g) * PP + kk * 8 + tig;
            a[0] = Ps[r0];          a[1] = Ps[r0 + 8 * PP];
            a[2] = Ps[r0 + 4];      a[3] = Ps[r0 + 8 * PP + 4];
            #pragma unroll
            for (int j = 0; j < 16; j++) {
                unsigned bq[2];
                int cb = j * 8 + g;
                bq[0] = Vs[(kk * 8 + tig    ) * VSP + cb];
                bq[1] = Vs[(kk * 8 + tig + 4) * VSP + cb];
                mma_tf32(o[j], a, bq);
            }
        }

        __syncthreads();                    // done reading V
        if (kt + 1 < nkt) issueV(kt + 1);
        else asm volatile("cp.async.commit_group;\n" ::: "memory");
    }

    const float inv0 = 1.f / l_i[0];
    const float inv1 = 1.f / l_i[1];
    #pragma unroll
    for (int j = 0; j < 16; j++) {
        int d = j * 8 + 2 * tig;
        size_t base0 = ((size_t)(b * T_ + qrow0    )) * C_ + h * HS_ + d;
        size_t base1 = ((size_t)(b * T_ + qrow0 + 8)) * C_ + h * HS_ + d;
        *(float2*)(ao + base0) = make_float2(o[j][0] * inv0, o[j][1] * inv0);
        *(float2*)(ao + base1) = make_float2(o[j][2] * inv1, o[j][3] * inv1);
    }
}

// ---------------------------------------------------------------------------
// Launch
// ---------------------------------------------------------------------------
extern "C" void kernel_launch(void* const* d_in, const int* in_sizes, int n_in,
                              void* d_out, int out_size)
{
    const float* x    = (const float*)d_in[0];
    const float* fc   = (const float*)d_in[1];
    const float* fs   = (const float*)d_in[2];
    const float* Wdq  = (const float*)d_in[3];
    const float* Wuq  = (const float*)d_in[4];
    const float* Wdkv = (const float*)d_in[5];
    const float* Wuk  = (const float*)d_in[6];
    const float* Wuv  = (const float*)d_in[7];
    const float* Wqr  = (const float*)d_in[8];
    const float* Wkr  = (const float*)d_in[9];
    const float* Wo   = (const float*)d_in[10];
    float* out = (float*)d_out;

    float *cq, *ckv, *q, *k, *v, *ao;
    cudaGetSymbolAddress((void**)&cq,  g_cq);
    cudaGetSymbolAddress((void**)&ckv, g_ckv);
    cudaGetSymbolAddress((void**)&q,   g_q);
    cudaGetSymbolAddress((void**)&k,   g_k);
    cudaGetSymbolAddress((void**)&v,   g_v);
    cudaGetSymbolAddress((void**)&ao,  g_ao);

    static bool attr_set = false;
    if (!attr_set) {
        cudaFuncSetAttribute(flash_attn, cudaFuncAttributeMaxDynamicSharedMemorySize,
                             FLASH_SMEM_BYTES);
        cudaFuncSetAttribute(gemm8<0>, cudaFuncAttributeMaxDynamicSharedMemorySize,
                             GEMM_SMEM_BYTES);
        cudaFuncSetAttribute(gemm8<5>, cudaFuncAttributeMaxDynamicSharedMemorySize,
                             GEMM_SMEM_BYTES);
        cudaFuncSetAttribute(gemm8<6>, cudaFuncAttributeMaxDynamicSharedMemorySize,
                             GEMM_SMEM_BYTES);
        cudaFuncSetAttribute(gemm8<7>, cudaFuncAttributeMaxDynamicSharedMemorySize,
                             GEMM_SMEM_BYTES);
        attr_set = true;
    }

    dim3 blk(256);

    // GEMM A: x -> [c_q | c_kv | rope-bcast k_r], N=1088, K=2048
    gemm8<5><<<dim3(9, 32), blk, GEMM_SMEM_BYTES>>>(
        x, Wdq, Wdkv, Wkr, 512, 1024, 1088, C_, C_, C_, nullptr, 0, fc, fs);

    // GEMM B: c_q -> [q_c | rope q_r], N=3072, K=512
    gemm8<6><<<dim3(24, 32), blk, GEMM_SMEM_BYTES>>>(
        cq, Wuq, Wqr, Wqr, 2048, 3072, 3072, NLQ_, NLQ_, NLQ_, nullptr, 0, fc, fs);

    // GEMM C: c_kv -> [k_c | v], N=4096, K=512
    gemm8<7><<<dim3(32, 32), blk, GEMM_SMEM_BYTES>>>(
        ckv, Wuk, Wuv, Wuv, 2048, 4096, 4096, NLKV_, NLKV_, NLKV_, nullptr, 0, fc, fs);

    // Fused flash attention
    dim3 gfa(B_ * H_, T_ / 128);
    flash_attn<<<gfa, 256, FLASH_SMEM_BYTES>>>(q, k, v, ao);

    // Output projection
    gemm8<0><<<dim3(16, 32), blk, GEMM_SMEM_BYTES>>>(
        ao, Wo, Wo, Wo, 4096, 8192, 2048, C_, C_, C_, out, C_, fc, fs);
}